// round 1
// baseline (speedup 1.0000x reference)
#include <cuda_runtime.h>
#include <math.h>

// ---------------- problem constants ----------------
constexpr int BATCH  = 2;
constexpr int SEQ    = 2048;
constexpr int CH     = 1024;
constexpr int FF     = 4096;
constexpr int VOCAB  = 32000;
constexpr int NLAYER = 6;
constexpr int NROWS  = BATCH * SEQ;   // 4096

// ---------------- scratch (device globals; no runtime allocation) ----------
__device__ float g_x  [NROWS * CH];
__device__ float g_h  [NROWS * CH];
__device__ float g_xk [NROWS * CH];
__device__ float g_xv [NROWS * CH];
__device__ float g_xr [NROWS * CH];
__device__ float g_k  [NROWS * CH];
__device__ float g_v  [NROWS * CH];
__device__ float g_r  [NROWS * CH];
__device__ float g_wkv[NROWS * CH];
__device__ float g_kk [NROWS * FF];
__device__ float g_rr [NROWS * CH];

// ---------------- layernorm -------------------------------------------------
__device__ __forceinline__ void ln_row_body(const float* __restrict__ xp,
                                            float* __restrict__ op,
                                            const float* __restrict__ w,
                                            const float* __restrict__ b)
{
    float s = 0.f, s2 = 0.f;
    for (int i = threadIdx.x; i < CH; i += 256) {
        float v = xp[i];
        s  += v;
        s2 += v * v;
    }
#pragma unroll
    for (int o = 16; o > 0; o >>= 1) {
        s  += __shfl_down_sync(0xffffffffu, s,  o);
        s2 += __shfl_down_sync(0xffffffffu, s2, o);
    }
    __shared__ float sh[2][8];
    int warp = threadIdx.x >> 5, lane = threadIdx.x & 31;
    if (lane == 0) { sh[0][warp] = s; sh[1][warp] = s2; }
    __syncthreads();
    float tot = 0.f, tot2 = 0.f;
#pragma unroll
    for (int i = 0; i < 8; i++) { tot += sh[0][i]; tot2 += sh[1][i]; }
    float mean = tot * (1.f / CH);
    float var  = tot2 * (1.f / CH) - mean * mean;
    float inv  = rsqrtf(fmaxf(var, 0.f) + 1e-5f);
    for (int i = threadIdx.x; i < CH; i += 256) {
        op[i] = (xp[i] - mean) * inv * w[i] + b[i];
    }
}

__global__ void ln_rows(const float* __restrict__ in, float* __restrict__ out,
                        const float* __restrict__ w, const float* __restrict__ b)
{
    int row = blockIdx.x;
    ln_row_body(in + (size_t)row * CH, out + (size_t)row * CH, w, b);
}

__global__ void embed_ln0(const int* __restrict__ idx, const float* __restrict__ emb,
                          const float* __restrict__ w, const float* __restrict__ b,
                          float* __restrict__ out)
{
    int row = blockIdx.x;
    int tok = idx[row];
    ln_row_body(emb + (size_t)tok * CH, out + (size_t)row * CH, w, b);
}

// ---------------- token-shift mixing ----------------------------------------
__global__ void mix_time_kernel(const float* __restrict__ h,
                                const float* __restrict__ mk,
                                const float* __restrict__ mv,
                                const float* __restrict__ mr,
                                float* __restrict__ xk,
                                float* __restrict__ xv,
                                float* __restrict__ xr)
{
    int i = blockIdx.x * blockDim.x + threadIdx.x;
    if (i >= NROWS * CH) return;
    int c = i & (CH - 1);
    int t = (i >> 10) & (SEQ - 1);   // CH = 1024 = 2^10
    float hv = h[i];
    float hp = (t == 0) ? 0.f : h[i - CH];
    float a = mk[c]; xk[i] = hv * a + hp * (1.f - a);
    float m = mv[c]; xv[i] = hv * m + hp * (1.f - m);
    float r = mr[c]; xr[i] = hv * r + hp * (1.f - r);
}

__global__ void mix_chan_kernel(const float* __restrict__ h,
                                const float* __restrict__ mk,
                                const float* __restrict__ mr,
                                float* __restrict__ xk,
                                float* __restrict__ xr)
{
    int i = blockIdx.x * blockDim.x + threadIdx.x;
    if (i >= NROWS * CH) return;
    int c = i & (CH - 1);
    int t = (i >> 10) & (SEQ - 1);
    float hv = h[i];
    float hp = (t == 0) ? 0.f : h[i - CH];
    float a = mk[c]; xk[i] = hv * a + hp * (1.f - a);
    float r = mr[c]; xr[i] = hv * r + hp * (1.f - r);
}

// ---------------- gating: wkv *= sigmoid(r) ---------------------------------
__global__ void gate_kernel(const float* __restrict__ r, float* __restrict__ wkv)
{
    int i = blockIdx.x * blockDim.x + threadIdx.x;
    if (i >= NROWS * CH) return;
    wkv[i] *= 1.f / (1.f + expf(-r[i]));
}

// ---------------- WKV recurrence (sequential over T per channel) ------------
__global__ void wkv_kernel(const float* __restrict__ td, const float* __restrict__ tf,
                           const float* __restrict__ k, const float* __restrict__ v,
                           float* __restrict__ y)
{
    int g = blockIdx.x * blockDim.x + threadIdx.x;
    if (g >= BATCH * CH) return;
    int b = g / CH, c = g % CH;
    float w = -expf(td[c]);
    float u = tf[c];
    const float* kp = k + (size_t)b * SEQ * CH + c;
    const float* vp = v + (size_t)b * SEQ * CH + c;
    float*       yp = y + (size_t)b * SEQ * CH + c;
    float a = 0.f, bb = 0.f, p = -1e38f;
    for (int t = 0; t < SEQ; t++) {
        float kt = kp[(size_t)t * CH];
        float vt = vp[(size_t)t * CH];
        float ww = u + kt;
        float q  = fmaxf(p, ww);
        float e1 = expf(p - q);
        float e2 = expf(ww - q);
        yp[(size_t)t * CH] = (e1 * a + e2 * vt) / (e1 * bb + e2);
        float ww2 = p + w;
        float q2  = fmaxf(ww2, kt);
        float e1b = expf(ww2 - q2);
        float e2b = expf(kt - q2);
        a  = e1b * a  + e2b * vt;
        bb = e1b * bb + e2b;
        p  = q2;
    }
}

// ---------------- tiled fp32 NT GEMM: C[M,N] = A[M,K] * B[N,K]^T -------------
// A and B are both K-contiguous (row-major [M,K] / [N,K]).
// 128x128 block tile, BK=16, 256 threads, 8x8 per-thread register tile,
// double-buffered shared memory. M,N multiples of 128; K multiple of 16.
constexpr int GBM = 128, GBN = 128, GBK = 16;

enum { EPI_NONE = 0, EPI_RELUSQ = 1, EPI_SIGMOID = 2, EPI_ADD = 3, EPI_ADD_MUL = 4 };

template <int EPI>
__global__ void __launch_bounds__(256, 2)
gemm_nt(const float* __restrict__ A, const float* __restrict__ Bw,
        float* __restrict__ Co, const float* __restrict__ Res,
        const float* __restrict__ Mul, int M, int N, int K)
{
    __shared__ float As[2][GBK][GBM + 4];
    __shared__ float Bs[2][GBK][GBN + 4];

    const int tid = threadIdx.x;
    const int tx  = tid & 15;   // col group (8 cols each)
    const int ty  = tid >> 4;   // row group (8 rows each)
    const int bm  = blockIdx.y;
    const int bn  = blockIdx.x;

    const float* Ab = A  + (size_t)bm * GBM * K;
    const float* Bb = Bw + (size_t)bn * GBN * K;

    const int lrow = tid >> 2;        // 0..63
    const int lcol = (tid & 3) * 4;   // 0,4,8,12

    float acc[8][8];
#pragma unroll
    for (int i = 0; i < 8; i++)
#pragma unroll
        for (int j = 0; j < 8; j++) acc[i][j] = 0.f;

    float4 ra0, ra1, rb0, rb1;

    // prologue: tile 0 -> buf 0
    ra0 = *(const float4*)(Ab + (size_t)lrow * K + lcol);
    ra1 = *(const float4*)(Ab + (size_t)(lrow + 64) * K + lcol);
    rb0 = *(const float4*)(Bb + (size_t)lrow * K + lcol);
    rb1 = *(const float4*)(Bb + (size_t)(lrow + 64) * K + lcol);
    As[0][lcol + 0][lrow]      = ra0.x; As[0][lcol + 1][lrow]      = ra0.y;
    As[0][lcol + 2][lrow]      = ra0.z; As[0][lcol + 3][lrow]      = ra0.w;
    As[0][lcol + 0][lrow + 64] = ra1.x; As[0][lcol + 1][lrow + 64] = ra1.y;
    As[0][lcol + 2][lrow + 64] = ra1.z; As[0][lcol + 3][lrow + 64] = ra1.w;
    Bs[0][lcol + 0][lrow]      = rb0.x; Bs[0][lcol + 1][lrow]      = rb0.y;
    Bs[0][lcol + 2][lrow]      = rb0.z; Bs[0][lcol + 3][lrow]      = rb0.w;
    Bs[0][lcol + 0][lrow + 64] = rb1.x; Bs[0][lcol + 1][lrow + 64] = rb1.y;
    Bs[0][lcol + 2][lrow + 64] = rb1.z; Bs[0][lcol + 3][lrow + 64] = rb1.w;
    __syncthreads();

    const int ntiles = K / GBK;
    int buf = 0;
    for (int kt = 0; kt < ntiles; kt++) {
        if (kt + 1 < ntiles) {
            const float* Ap = Ab + (size_t)(kt + 1) * GBK;
            const float* Bp = Bb + (size_t)(kt + 1) * GBK;
            ra0 = *(const float4*)(Ap + (size_t)lrow * K + lcol);
            ra1 = *(const float4*)(Ap + (size_t)(lrow + 64) * K + lcol);
            rb0 = *(const float4*)(Bp + (size_t)lrow * K + lcol);
            rb1 = *(const float4*)(Bp + (size_t)(lrow + 64) * K + lcol);
        }
#pragma unroll
        for (int kk = 0; kk < GBK; kk++) {
            float4 a0 = *(const float4*)&As[buf][kk][ty * 8];
            float4 a1 = *(const float4*)&As[buf][kk][ty * 8 + 4];
            float4 b0 = *(const float4*)&Bs[buf][kk][tx * 8];
            float4 b1 = *(const float4*)&Bs[buf][kk][tx * 8 + 4];
            float av[8] = {a0.x, a0.y, a0.z, a0.w, a1.x, a1.y, a1.z, a1.w};
            float bv[8] = {b0.x, b0.y, b0.z, b0.w, b1.x, b1.y, b1.z, b1.w};
#pragma unroll
            for (int i = 0; i < 8; i++)
#pragma unroll
                for (int j = 0; j < 8; j++)
                    acc[i][j] = fmaf(av[i], bv[j], acc[i][j]);
        }
        if (kt + 1 < ntiles) {
            int nb = buf ^ 1;
            As[nb][lcol + 0][lrow]      = ra0.x; As[nb][lcol + 1][lrow]      = ra0.y;
            As[nb][lcol + 2][lrow]      = ra0.z; As[nb][lcol + 3][lrow]      = ra0.w;
            As[nb][lcol + 0][lrow + 64] = ra1.x; As[nb][lcol + 1][lrow + 64] = ra1.y;
            As[nb][lcol + 2][lrow + 64] = ra1.z; As[nb][lcol + 3][lrow + 64] = ra1.w;
            Bs[nb][lcol + 0][lrow]      = rb0.x; Bs[nb][lcol + 1][lrow]      = rb0.y;
            Bs[nb][lcol + 2][lrow]      = rb0.z; Bs[nb][lcol + 3][lrow]      = rb0.w;
            Bs[nb][lcol + 0][lrow + 64] = rb1.x; Bs[nb][lcol + 1][lrow + 64] = rb1.y;
            Bs[nb][lcol + 2][lrow + 64] = rb1.z; Bs[nb][lcol + 3][lrow + 64] = rb1.w;
            __syncthreads();
            buf = nb;
        }
    }

    // epilogue
    const int crow0 = bm * GBM + ty * 8;
    const int ccol0 = bn * GBN + tx * 8;
#pragma unroll
    for (int i = 0; i < 8; i++) {
        size_t off = (size_t)(crow0 + i) * N + ccol0;
#pragma unroll
        for (int j = 0; j < 8; j++) {
            float val = acc[i][j];
            if (EPI == EPI_RELUSQ) {
                float t = val > 0.f ? val : 0.f;
                val = t * t;
            } else if (EPI == EPI_SIGMOID) {
                val = 1.f / (1.f + expf(-val));
            } else if (EPI == EPI_ADD) {
                val = Res[off + j] + val;
            } else if (EPI == EPI_ADD_MUL) {
                val = Res[off + j] + Mul[off + j] * val;
            }
            Co[off + j] = val;
        }
    }
}

template <int EPI>
static void launch_gemm(const float* A, const float* Bw, float* Co,
                        const float* Res, const float* Mul, int M, int N, int K)
{
    dim3 grid(N / GBN, M / GBM), blk(256);
    gemm_nt<EPI><<<grid, blk>>>(A, Bw, Co, Res, Mul, M, N, K);
}

// ---------------- host orchestration ----------------------------------------
extern "C" void kernel_launch(void* const* d_in, const int* in_sizes, int n_in,
                              void* d_out, int out_size)
{
    (void)in_sizes; (void)n_in; (void)out_size;

    const int*   idx        = (const int*)  d_in[0];
    const float* emb        = (const float*)d_in[1];
    const float* ln0_w      = (const float*)d_in[2];
    const float* ln0_b      = (const float*)d_in[3];
    const float* ln1_w      = (const float*)d_in[4];
    const float* ln1_b      = (const float*)d_in[5];
    const float* ln2_w      = (const float*)d_in[6];
    const float* ln2_b      = (const float*)d_in[7];
    const float* time_decay = (const float*)d_in[8];
    const float* time_first = (const float*)d_in[9];
    const float* tmk        = (const float*)d_in[10];
    const float* tmv        = (const float*)d_in[11];
    const float* tmr        = (const float*)d_in[12];
    const float* att_Wk     = (const float*)d_in[13];
    const float* att_Wv     = (const float*)d_in[14];
    const float* att_Wr     = (const float*)d_in[15];
    const float* att_Wo     = (const float*)d_in[16];
    const float* fmk        = (const float*)d_in[17];
    const float* fmr        = (const float*)d_in[18];
    const float* ffn_Wk     = (const float*)d_in[19];
    const float* ffn_Wr     = (const float*)d_in[20];
    const float* ffn_Wv     = (const float*)d_in[21];
    const float* ln_out_w   = (const float*)d_in[22];
    const float* ln_out_b   = (const float*)d_in[23];
    const float* head_w     = (const float*)d_in[24];
    float* out = (float*)d_out;

    float *x, *h, *xk, *xv, *xr, *kb, *vb, *rb, *wkvb, *kkb, *rrb;
    cudaGetSymbolAddress((void**)&x,    g_x);
    cudaGetSymbolAddress((void**)&h,    g_h);
    cudaGetSymbolAddress((void**)&xk,   g_xk);
    cudaGetSymbolAddress((void**)&xv,   g_xv);
    cudaGetSymbolAddress((void**)&xr,   g_xr);
    cudaGetSymbolAddress((void**)&kb,   g_k);
    cudaGetSymbolAddress((void**)&vb,   g_v);
    cudaGetSymbolAddress((void**)&rb,   g_r);
    cudaGetSymbolAddress((void**)&wkvb, g_wkv);
    cudaGetSymbolAddress((void**)&kkb,  g_kk);
    cudaGetSymbolAddress((void**)&rrb,  g_rr);

    const int EB = (NROWS * CH + 255) / 256;

    // embedding + ln0
    embed_ln0<<<NROWS, 256>>>(idx, emb, ln0_w, ln0_b, x);

    for (int i = 0; i < NLAYER; i++) {
        size_t oc  = (size_t)i * CH;
        size_t occ = (size_t)i * CH * CH;
        size_t ohc = (size_t)i * FF * CH;

        // ---- TimeMix ----
        ln_rows<<<NROWS, 256>>>(x, h, ln1_w + oc, ln1_b + oc);
        mix_time_kernel<<<EB, 256>>>(h, tmk + oc, tmv + oc, tmr + oc, xk, xv, xr);
        launch_gemm<EPI_NONE>(xk, att_Wk + occ, kb, nullptr, nullptr, NROWS, CH, CH);
        launch_gemm<EPI_NONE>(xv, att_Wv + occ, vb, nullptr, nullptr, NROWS, CH, CH);
        launch_gemm<EPI_NONE>(xr, att_Wr + occ, rb, nullptr, nullptr, NROWS, CH, CH);
        wkv_kernel<<<(BATCH * CH + 255) / 256, 256>>>(time_decay + oc, time_first + oc,
                                                      kb, vb, wkvb);
        gate_kernel<<<EB, 256>>>(rb, wkvb);
        launch_gemm<EPI_ADD>(wkvb, att_Wo + occ, x, x, nullptr, NROWS, CH, CH);

        // ---- ChannelMix ----
        ln_rows<<<NROWS, 256>>>(x, h, ln2_w + oc, ln2_b + oc);
        mix_chan_kernel<<<EB, 256>>>(h, fmk + oc, fmr + oc, xk, xr);
        launch_gemm<EPI_RELUSQ>(xk, ffn_Wk + ohc, kkb, nullptr, nullptr, NROWS, FF, CH);
        launch_gemm<EPI_SIGMOID>(xr, ffn_Wr + occ, rrb, nullptr, nullptr, NROWS, CH, CH);
        launch_gemm<EPI_ADD_MUL>(kkb, ffn_Wv + ohc, x, x, rrb, NROWS, CH, FF);
    }

    // final LN + head projection
    ln_rows<<<NROWS, 256>>>(x, h, ln_out_w, ln_out_b);
    launch_gemm<EPI_NONE>(h, head_w, out, nullptr, nullptr, NROWS, VOCAB, CH);
}

// round 3
// speedup vs baseline: 2.2118x; 2.2118x over previous
#include <cuda_runtime.h>
#include <cuda_bf16.h>
#include <math.h>
#include <stdint.h>

// ---------------- problem constants ----------------
constexpr int BATCH  = 2;
constexpr int SEQ    = 2048;
constexpr int CH     = 1024;
constexpr int FF     = 4096;
constexpr int VOCAB  = 32000;
constexpr int NLAYER = 6;
constexpr int NROWS  = BATCH * SEQ;   // 4096

// weight pool layout (bf16 hi/lo twins), grouped per-tensor across layers
constexpr size_t CCH = (size_t)CH * CH;     // 1,048,576
constexpr size_t FCH = (size_t)FF * CH;     // 4,194,304
constexpr size_t OW_ATTK = 0;
constexpr size_t OW_ATTV = OW_ATTK + 6 * CCH;
constexpr size_t OW_ATTR = OW_ATTV + 6 * CCH;
constexpr size_t OW_ATTO = OW_ATTR + 6 * CCH;
constexpr size_t OW_FK   = OW_ATTO + 6 * CCH;
constexpr size_t OW_FV   = OW_FK   + 6 * FCH;
constexpr size_t OW_FR   = OW_FV   + 6 * FCH;
constexpr size_t OW_HEAD = OW_FR   + 6 * CCH;
constexpr size_t W_TOTAL = OW_HEAD + (size_t)VOCAB * CH;  // 114,556,928

// ---------------- scratch (device globals; no runtime allocation) ----------
__device__ __align__(256) float g_x  [NROWS * CH];
__device__ __align__(256) float g_h  [NROWS * CH];
__device__ __align__(256) float g_k  [NROWS * CH];
__device__ __align__(256) float g_v  [NROWS * CH];
__device__ __align__(256) float g_r  [NROWS * CH];
__device__ __align__(256) float g_wkv[NROWS * CH];
__device__ __align__(256) float g_rr [NROWS * CH];

__device__ __align__(256) __nv_bfloat16 g_whi[W_TOTAL];
__device__ __align__(256) __nv_bfloat16 g_wlo[W_TOTAL];

__device__ __align__(256) __nv_bfloat16 g_xkh[NROWS * CH], g_xkl[NROWS * CH];
__device__ __align__(256) __nv_bfloat16 g_xvh[NROWS * CH], g_xvl[NROWS * CH];
__device__ __align__(256) __nv_bfloat16 g_xrh[NROWS * CH], g_xrl[NROWS * CH];
__device__ __align__(256) __nv_bfloat16 g_gwh[NROWS * CH], g_gwl[NROWS * CH];
__device__ __align__(256) __nv_bfloat16 g_hhh[NROWS * CH], g_hhl[NROWS * CH];
__device__ __align__(256) __nv_bfloat16 g_kkh[NROWS * FF], g_kkl[NROWS * FF];

// ---------------- small helpers ---------------------------------------------
__device__ __forceinline__ uint32_t smem_u32(const void* p) {
    uint32_t a;
    asm("{ .reg .u64 t; cvta.to.shared.u64 t, %1; cvt.u32.u64 %0, t; }"
        : "=r"(a) : "l"(p));
    return a;
}
__device__ __forceinline__ void split1(float v, __nv_bfloat16& h, __nv_bfloat16& l) {
    h = __float2bfloat16_rn(v);
    l = __float2bfloat16_rn(v - __bfloat162float(h));
}
__device__ __forceinline__ void store_pair(__nv_bfloat16* __restrict__ H,
                                           __nv_bfloat16* __restrict__ L,
                                           size_t e, float v0, float v1) {
    __nv_bfloat16 h0, l0, h1, l1;
    split1(v0, h0, l0); split1(v1, h1, l1);
    *reinterpret_cast<__nv_bfloat162*>(H + e) = __halves2bfloat162(h0, h1);
    *reinterpret_cast<__nv_bfloat162*>(L + e) = __halves2bfloat162(l0, l1);
}

// ---------------- weight fp32 -> bf16 hi/lo split ----------------------------
__global__ void cvt_split(const float* __restrict__ in,
                          __nv_bfloat16* __restrict__ hi,
                          __nv_bfloat16* __restrict__ lo, int n4)
{
    int i = blockIdx.x * 256 + threadIdx.x;
    if (i >= n4) return;
    float4 v = reinterpret_cast<const float4*>(in)[i];
    __nv_bfloat16 h0, l0, h1, l1, h2, l2, h3, l3;
    split1(v.x, h0, l0); split1(v.y, h1, l1);
    split1(v.z, h2, l2); split1(v.w, h3, l3);
    __nv_bfloat162 ha = __halves2bfloat162(h0, h1), hb = __halves2bfloat162(h2, h3);
    __nv_bfloat162 la = __halves2bfloat162(l0, l1), lb = __halves2bfloat162(l2, l3);
    uint2 hv, lv;
    hv.x = *reinterpret_cast<uint32_t*>(&ha); hv.y = *reinterpret_cast<uint32_t*>(&hb);
    lv.x = *reinterpret_cast<uint32_t*>(&la); lv.y = *reinterpret_cast<uint32_t*>(&lb);
    reinterpret_cast<uint2*>(hi)[i] = hv;
    reinterpret_cast<uint2*>(lo)[i] = lv;
}

// ================= tensor-core GEMM (mma.sync bf16, 3-term split) ===========
// C[M,N] = A[M,K] * B[N,K]^T ; A,B given as bf16 hi/lo twins.
// CTA tile 128x256, BK=64, 256 threads, 8 warps as 2x4 (warp tile 64x64).
constexpr int ST_A  = 128 * 64 * 2;            // 16384 B per A split tile
constexpr int ST_B  = 256 * 64 * 2;            // 32768 B per B split tile
constexpr int STAGE = 2 * ST_A + 2 * ST_B;     // 98304
constexpr int GSMEM = 2 * STAGE;               // 196608

enum { EPI_NONE = 0, EPI_RELUSQ = 1, EPI_SIGMOID = 2, EPI_ADD = 3, EPI_ADD_MUL = 4 };

struct GJob {
    const __nv_bfloat16 *Ah, *Al, *Bh, *Bl;
    float* C;
    __nv_bfloat16 *Ch, *Cl;
};
struct GJobs { GJob j[3]; };

__device__ __forceinline__ void cp16(uint32_t dst, const void* src) {
    asm volatile("cp.async.cg.shared.global [%0], [%1], 16;" :: "r"(dst), "l"(src));
}
__device__ __forceinline__ void ldsm4(uint32_t* r, uint32_t addr) {
    asm volatile("ldmatrix.sync.aligned.m8n8.x4.shared.b16 {%0,%1,%2,%3}, [%4];"
                 : "=r"(r[0]), "=r"(r[1]), "=r"(r[2]), "=r"(r[3]) : "r"(addr));
}
__device__ __forceinline__ void mma16816(float* c, const uint32_t* a, const uint32_t* b) {
    asm volatile(
        "mma.sync.aligned.m16n8k16.row.col.f32.bf16.bf16.f32 "
        "{%0,%1,%2,%3}, {%4,%5,%6,%7}, {%8,%9}, {%0,%1,%2,%3};"
        : "+f"(c[0]), "+f"(c[1]), "+f"(c[2]), "+f"(c[3])
        : "r"(a[0]), "r"(a[1]), "r"(a[2]), "r"(a[3]), "r"(b[0]), "r"(b[1]));
}

template <int EPI>
__global__ void __launch_bounds__(256, 1)
gemm_mma(GJobs jobs, const float* __restrict__ Res, const float* __restrict__ Mul,
         int M, int N, int K)
{
    extern __shared__ char smem[];
    const uint32_t sb = smem_u32(smem);
    const GJob jb = jobs.j[blockIdx.z];

    const int tid  = threadIdx.x;
    const int lane = tid & 31;
    const int w    = tid >> 5;
    const int wr   = w >> 2;          // 0..1  (M)
    const int wc   = w & 3;           // 0..3  (N)
    const int bm   = blockIdx.y;
    const int bn   = blockIdx.x;

    const int nk = K >> 6;

    // ---- cp.async stage fill -------------------------------------------------
    const int jj = tid & 7;           // 16B chunk within 128B row
    const int rg = tid >> 3;          // 0..31
    const __nv_bfloat16* Agh = jb.Ah + (size_t)bm * 128 * K;
    const __nv_bfloat16* Agl = jb.Al + (size_t)bm * 128 * K;
    const __nv_bfloat16* Bgh = jb.Bh + (size_t)bn * 256 * K;
    const __nv_bfloat16* Bgl = jb.Bl + (size_t)bn * 256 * K;

    auto issue = [&](int kt, int st) {
        const uint32_t base = sb + (uint32_t)st * STAGE;
        const size_t kof = (size_t)kt * 64 + jj * 8;
#pragma unroll
        for (int it = 0; it < 4; it++) {
            int r = rg + it * 32;
            uint32_t d = base + r * 128 + (uint32_t)((jj ^ (r & 7)) << 4);
            cp16(d,        Agh + (size_t)r * K + kof);
            cp16(d + ST_A, Agl + (size_t)r * K + kof);
        }
#pragma unroll
        for (int it = 0; it < 8; it++) {
            int r = rg + it * 32;
            uint32_t d = base + 2 * ST_A + r * 128 + (uint32_t)((jj ^ (r & 7)) << 4);
            cp16(d,        Bgh + (size_t)r * K + kof);
            cp16(d + ST_B, Bgl + (size_t)r * K + kof);
        }
    };

    // ---- fragment address precompute ------------------------------------------
    const int sel = lane >> 3, r8 = lane & 7;
    uint32_t a_row[4], b_row[4], a_chk[4], b_chk[4];
#pragma unroll
    for (int mt = 0; mt < 4; mt++)
        a_row[mt] = (uint32_t)((wr * 64 + mt * 16 + (sel & 1) * 8 + r8) * 128);
#pragma unroll
    for (int np = 0; np < 4; np++)
        b_row[np] = (uint32_t)((wc * 64 + np * 16 + (sel >> 1) * 8 + r8) * 128);
#pragma unroll
    for (int ks = 0; ks < 4; ks++) {
        a_chk[ks] = (uint32_t)(((ks * 2 + (sel >> 1)) ^ r8) << 4);
        b_chk[ks] = (uint32_t)(((ks * 2 + (sel & 1)) ^ r8) << 4);
    }

    float acc[4][8][4];
#pragma unroll
    for (int mt = 0; mt < 4; mt++)
#pragma unroll
        for (int nt = 0; nt < 8; nt++)
#pragma unroll
            for (int q = 0; q < 4; q++) acc[mt][nt][q] = 0.f;

    auto compute = [&](int st) {
        const uint32_t sbase = sb + (uint32_t)st * STAGE;
#pragma unroll
        for (int ks = 0; ks < 4; ks++) {
            uint32_t ah[4][4], al[4][4];
#pragma unroll
            for (int mt = 0; mt < 4; mt++) {
                uint32_t ad = sbase + a_row[mt] + a_chk[ks];
                ldsm4(ah[mt], ad);
                ldsm4(al[mt], ad + ST_A);
            }
            uint32_t bh[8][2], bl[8][2];
#pragma unroll
            for (int np = 0; np < 4; np++) {
                uint32_t bd = sbase + 2 * ST_A + b_row[np] + b_chk[ks];
                uint32_t t[4];
                ldsm4(t, bd);
                bh[2*np][0] = t[0]; bh[2*np][1] = t[1];
                bh[2*np+1][0] = t[2]; bh[2*np+1][1] = t[3];
                ldsm4(t, bd + ST_B);
                bl[2*np][0] = t[0]; bl[2*np][1] = t[1];
                bl[2*np+1][0] = t[2]; bl[2*np+1][1] = t[3];
            }
#pragma unroll
            for (int mt = 0; mt < 4; mt++)
#pragma unroll
                for (int nt = 0; nt < 8; nt++) {
                    mma16816(acc[mt][nt], ah[mt], bh[nt]);
                    mma16816(acc[mt][nt], ah[mt], bl[nt]);
                    mma16816(acc[mt][nt], al[mt], bh[nt]);
                }
        }
    };

    // ---- pipelined mainloop ----------------------------------------------------
    issue(0, 0);
    asm volatile("cp.async.commit_group;" ::: "memory");
    for (int kt = 0; kt < nk; kt++) {
        if (kt + 1 < nk) {
            issue(kt + 1, (kt + 1) & 1);
            asm volatile("cp.async.commit_group;" ::: "memory");
            asm volatile("cp.async.wait_group 1;" ::: "memory");
        } else {
            asm volatile("cp.async.wait_group 0;" ::: "memory");
        }
        __syncthreads();
        compute(kt & 1);
        __syncthreads();
    }

    // ---- epilogue ----------------------------------------------------------------
    const int r0    = bm * 128 + wr * 64 + (lane >> 2);
    const int cbase = bn * 256 + wc * 64 + (lane & 3) * 2;
#pragma unroll
    for (int mt = 0; mt < 4; mt++) {
#pragma unroll
        for (int nt = 0; nt < 8; nt++) {
            int r = r0 + mt * 16;
            int c = cbase + nt * 8;
#pragma unroll
            for (int half = 0; half < 2; half++) {
                int rr2 = r + half * 8;
                float v0 = acc[mt][nt][half * 2 + 0];
                float v1 = acc[mt][nt][half * 2 + 1];
                size_t off = (size_t)rr2 * N + c;
                if (EPI == EPI_RELUSQ) {
                    float t0 = v0 > 0.f ? v0 : 0.f; v0 = t0 * t0;
                    float t1 = v1 > 0.f ? v1 : 0.f; v1 = t1 * t1;
                    store_pair(jb.Ch, jb.Cl, off, v0, v1);
                } else {
                    if (EPI == EPI_SIGMOID) {
                        v0 = 1.f / (1.f + expf(-v0));
                        v1 = 1.f / (1.f + expf(-v1));
                    } else if (EPI == EPI_ADD) {
                        float2 rv = *(const float2*)(Res + off);
                        v0 += rv.x; v1 += rv.y;
                    } else if (EPI == EPI_ADD_MUL) {
                        float2 rv = *(const float2*)(Res + off);
                        float2 mv = *(const float2*)(Mul + off);
                        v0 = rv.x + mv.x * v0; v1 = rv.y + mv.y * v1;
                    }
                    *(float2*)(jb.C + off) = make_float2(v0, v1);
                }
            }
        }
    }
}

// ---------------- layernorm -------------------------------------------------
__device__ __forceinline__ void ln_stats(const float* __restrict__ xp,
                                         float& mean, float& inv)
{
    float s = 0.f, s2 = 0.f;
    for (int i = threadIdx.x; i < CH; i += 256) {
        float v = xp[i];
        s += v; s2 += v * v;
    }
#pragma unroll
    for (int o = 16; o > 0; o >>= 1) {
        s  += __shfl_down_sync(0xffffffffu, s,  o);
        s2 += __shfl_down_sync(0xffffffffu, s2, o);
    }
    __shared__ float sh[2][8];
    int warp = threadIdx.x >> 5, lane = threadIdx.x & 31;
    if (lane == 0) { sh[0][warp] = s; sh[1][warp] = s2; }
    __syncthreads();
    float tot = 0.f, tot2 = 0.f;
#pragma unroll
    for (int i = 0; i < 8; i++) { tot += sh[0][i]; tot2 += sh[1][i]; }
    mean = tot * (1.f / CH);
    float var = tot2 * (1.f / CH) - mean * mean;
    inv = rsqrtf(fmaxf(var, 0.f) + 1e-5f);
}

__global__ void ln_rows(const float* __restrict__ in, float* __restrict__ out,
                        const float* __restrict__ w, const float* __restrict__ b)
{
    const float* xp = in + (size_t)blockIdx.x * CH;
    float* op = out + (size_t)blockIdx.x * CH;
    float mean, inv;
    ln_stats(xp, mean, inv);
    for (int i = threadIdx.x; i < CH; i += 256)
        op[i] = (xp[i] - mean) * inv * w[i] + b[i];
}

__global__ void ln_rows_pair(const float* __restrict__ in,
                             __nv_bfloat16* __restrict__ oh,
                             __nv_bfloat16* __restrict__ ol,
                             const float* __restrict__ w, const float* __restrict__ b)
{
    const size_t row = blockIdx.x;
    const float* xp = in + row * CH;
    float mean, inv;
    ln_stats(xp, mean, inv);
    for (int i = threadIdx.x * 2; i < CH; i += 512) {
        float v0 = (xp[i]   - mean) * inv * w[i]   + b[i];
        float v1 = (xp[i+1] - mean) * inv * w[i+1] + b[i+1];
        store_pair(oh, ol, row * CH + i, v0, v1);
    }
}

__global__ void embed_ln0(const int* __restrict__ idx, const float* __restrict__ emb,
                          const float* __restrict__ w, const float* __restrict__ b,
                          float* __restrict__ out)
{
    int tok = idx[blockIdx.x];
    const float* xp = emb + (size_t)tok * CH;
    float* op = out + (size_t)blockIdx.x * CH;
    float mean, inv;
    ln_stats(xp, mean, inv);
    for (int i = threadIdx.x; i < CH; i += 256)
        op[i] = (xp[i] - mean) * inv * w[i] + b[i];
}

// ---------------- token-shift mixing (emit bf16 hi/lo pairs) -----------------
__global__ void mix_time_kernel(const float* __restrict__ h,
                                const float* __restrict__ mk,
                                const float* __restrict__ mv,
                                const float* __restrict__ mr,
                                __nv_bfloat16* __restrict__ xkh, __nv_bfloat16* __restrict__ xkl,
                                __nv_bfloat16* __restrict__ xvh, __nv_bfloat16* __restrict__ xvl,
                                __nv_bfloat16* __restrict__ xrh, __nv_bfloat16* __restrict__ xrl)
{
    int p = blockIdx.x * blockDim.x + threadIdx.x;
    if (p >= NROWS * CH / 2) return;
    size_t e = (size_t)p * 2;
    int c = (int)(e & (CH - 1));
    int t = (int)((e >> 10) & (SEQ - 1));
    float h0 = h[e], h1 = h[e + 1];
    float p0 = (t == 0) ? 0.f : h[e - CH];
    float p1 = (t == 0) ? 0.f : h[e - CH + 1];
    float a0 = mk[c], a1 = mk[c+1];
    store_pair(xkh, xkl, e, h0 * a0 + p0 * (1.f - a0), h1 * a1 + p1 * (1.f - a1));
    float m0 = mv[c], m1 = mv[c+1];
    store_pair(xvh, xvl, e, h0 * m0 + p0 * (1.f - m0), h1 * m1 + p1 * (1.f - m1));
    float r0 = mr[c], r1 = mr[c+1];
    store_pair(xrh, xrl, e, h0 * r0 + p0 * (1.f - r0), h1 * r1 + p1 * (1.f - r1));
}

__global__ void mix_chan_kernel(const float* __restrict__ h,
                                const float* __restrict__ mk,
                                const float* __restrict__ mr,
                                __nv_bfloat16* __restrict__ xkh, __nv_bfloat16* __restrict__ xkl,
                                __nv_bfloat16* __restrict__ xrh, __nv_bfloat16* __restrict__ xrl)
{
    int p = blockIdx.x * blockDim.x + threadIdx.x;
    if (p >= NROWS * CH / 2) return;
    size_t e = (size_t)p * 2;
    int c = (int)(e & (CH - 1));
    int t = (int)((e >> 10) & (SEQ - 1));
    float h0 = h[e], h1 = h[e + 1];
    float p0 = (t == 0) ? 0.f : h[e - CH];
    float p1 = (t == 0) ? 0.f : h[e - CH + 1];
    float a0 = mk[c], a1 = mk[c+1];
    store_pair(xkh, xkl, e, h0 * a0 + p0 * (1.f - a0), h1 * a1 + p1 * (1.f - a1));
    float r0 = mr[c], r1 = mr[c+1];
    store_pair(xrh, xrl, e, h0 * r0 + p0 * (1.f - r0), h1 * r1 + p1 * (1.f - r1));
}

// ---------------- gating: out = sigmoid(r) * wkv (bf16 pair) -----------------
__global__ void gate_pair(const float* __restrict__ r, const float* __restrict__ wkv,
                          __nv_bfloat16* __restrict__ gh, __nv_bfloat16* __restrict__ gl)
{
    int p = blockIdx.x * blockDim.x + threadIdx.x;
    if (p >= NROWS * CH / 2) return;
    size_t e = (size_t)p * 2;
    float v0 = wkv[e]     / (1.f + expf(-r[e]));
    float v1 = wkv[e + 1] / (1.f + expf(-r[e + 1]));
    store_pair(gh, gl, e, v0, v1);
}

// ---------------- WKV recurrence ---------------------------------------------
__global__ void wkv_kernel(const float* __restrict__ td, const float* __restrict__ tf,
                           const float* __restrict__ k, const float* __restrict__ v,
                           float* __restrict__ y)
{
    int g = blockIdx.x * blockDim.x + threadIdx.x;
    if (g >= BATCH * CH) return;
    int b = g / CH, c = g % CH;
    float w = -expf(td[c]);
    float u = tf[c];
    const float* kp = k + (size_t)b * SEQ * CH + c;
    const float* vp = v + (size_t)b * SEQ * CH + c;
    float*       yp = y + (size_t)b * SEQ * CH + c;
    float a = 0.f, bb = 0.f, p = -1e38f;
    for (int t = 0; t < SEQ; t++) {
        float kt = kp[(size_t)t * CH];
        float vt = vp[(size_t)t * CH];
        float ww = u + kt;
        float q  = fmaxf(p, ww);
        float e1 = expf(p - q);
        float e2 = expf(ww - q);
        yp[(size_t)t * CH] = (e1 * a + e2 * vt) / (e1 * bb + e2);
        float ww2 = p + w;
        float q2  = fmaxf(ww2, kt);
        float e1b = expf(ww2 - q2);
        float e2b = expf(kt - q2);
        a  = e1b * a  + e2b * vt;
        bb = e1b * bb + e2b;
        p  = q2;
    }
}

// ---------------- launch helpers ---------------------------------------------
template <int EPI>
static void launch_g(const __nv_bfloat16* Ah, const __nv_bfloat16* Al,
                     const __nv_bfloat16* Bh, const __nv_bfloat16* Bl,
                     float* C, __nv_bfloat16* Ch, __nv_bfloat16* Cl,
                     const float* Res, const float* Mul, int M, int N, int K)
{
    GJobs j;
    j.j[0] = { Ah, Al, Bh, Bl, C, Ch, Cl };
    j.j[1] = j.j[0]; j.j[2] = j.j[0];
    dim3 g(N / 256, M / 128, 1);
    gemm_mma<EPI><<<g, 256, GSMEM>>>(j, Res, Mul, M, N, K);
}

// ---------------- host orchestration ------------------------------------------
extern "C" void kernel_launch(void* const* d_in, const int* in_sizes, int n_in,
                              void* d_out, int out_size)
{
    (void)in_sizes; (void)n_in; (void)out_size;

    const int*   idx        = (const int*)  d_in[0];
    const float* emb        = (const float*)d_in[1];
    const float* ln0_w      = (const float*)d_in[2];
    const float* ln0_b      = (const float*)d_in[3];
    const float* ln1_w      = (const float*)d_in[4];
    const float* ln1_b      = (const float*)d_in[5];
    const float* ln2_w      = (const float*)d_in[6];
    const float* ln2_b      = (const float*)d_in[7];
    const float* time_decay = (const float*)d_in[8];
    const float* time_first = (const float*)d_in[9];
    const float* tmk        = (const float*)d_in[10];
    const float* tmv        = (const float*)d_in[11];
    const float* tmr        = (const float*)d_in[12];
    const float* att_Wk     = (const float*)d_in[13];
    const float* att_Wv     = (const float*)d_in[14];
    const float* att_Wr     = (const float*)d_in[15];
    const float* att_Wo     = (const float*)d_in[16];
    const float* fmk        = (const float*)d_in[17];
    const float* fmr        = (const float*)d_in[18];
    const float* ffn_Wk     = (const float*)d_in[19];
    const float* ffn_Wr     = (const float*)d_in[20];
    const float* ffn_Wv     = (const float*)d_in[21];
    const float* ln_out_w   = (const float*)d_in[22];
    const float* ln_out_b   = (const float*)d_in[23];
    const float* head_w     = (const float*)d_in[24];
    float* out = (float*)d_out;

    cudaFuncSetAttribute(gemm_mma<EPI_NONE>,    cudaFuncAttributeMaxDynamicSharedMemorySize, GSMEM);
    cudaFuncSetAttribute(gemm_mma<EPI_RELUSQ>,  cudaFuncAttributeMaxDynamicSharedMemorySize, GSMEM);
    cudaFuncSetAttribute(gemm_mma<EPI_SIGMOID>, cudaFuncAttributeMaxDynamicSharedMemorySize, GSMEM);
    cudaFuncSetAttribute(gemm_mma<EPI_ADD>,     cudaFuncAttributeMaxDynamicSharedMemorySize, GSMEM);
    cudaFuncSetAttribute(gemm_mma<EPI_ADD_MUL>, cudaFuncAttributeMaxDynamicSharedMemorySize, GSMEM);

    float *x, *h, *kb, *vb, *rb, *wkvb, *rrb;
    cudaGetSymbolAddress((void**)&x,    g_x);
    cudaGetSymbolAddress((void**)&h,    g_h);
    cudaGetSymbolAddress((void**)&kb,   g_k);
    cudaGetSymbolAddress((void**)&vb,   g_v);
    cudaGetSymbolAddress((void**)&rb,   g_r);
    cudaGetSymbolAddress((void**)&wkvb, g_wkv);
    cudaGetSymbolAddress((void**)&rrb,  g_rr);

    __nv_bfloat16 *whi, *wlo, *xkh, *xkl, *xvh, *xvl, *xrh, *xrl, *gwh, *gwl,
                  *hhh, *hhl, *kkh, *kkl;
    cudaGetSymbolAddress((void**)&whi, g_whi);
    cudaGetSymbolAddress((void**)&wlo, g_wlo);
    cudaGetSymbolAddress((void**)&xkh, g_xkh); cudaGetSymbolAddress((void**)&xkl, g_xkl);
    cudaGetSymbolAddress((void**)&xvh, g_xvh); cudaGetSymbolAddress((void**)&xvl, g_xvl);
    cudaGetSymbolAddress((void**)&xrh, g_xrh); cudaGetSymbolAddress((void**)&xrl, g_xrl);
    cudaGetSymbolAddress((void**)&gwh, g_gwh); cudaGetSymbolAddress((void**)&gwl, g_gwl);
    cudaGetSymbolAddress((void**)&hhh, g_hhh); cudaGetSymbolAddress((void**)&hhl, g_hhl);
    cudaGetSymbolAddress((void**)&kkh, g_kkh); cudaGetSymbolAddress((void**)&kkl, g_kkl);

    // ---- weight splitting (8 launches) ----
    auto cvt = [&](const float* src, size_t off, size_t n) {
        int n4 = (int)(n / 4);
        cvt_split<<<(n4 + 255) / 256, 256>>>(src, whi + off, wlo + off, n4);
    };
    cvt(att_Wk, OW_ATTK, 6 * CCH);
    cvt(att_Wv, OW_ATTV, 6 * CCH);
    cvt(att_Wr, OW_ATTR, 6 * CCH);
    cvt(att_Wo, OW_ATTO, 6 * CCH);
    cvt(ffn_Wk, OW_FK,   6 * FCH);
    cvt(ffn_Wv, OW_FV,   6 * FCH);
    cvt(ffn_Wr, OW_FR,   6 * CCH);
    cvt(head_w, OW_HEAD, (size_t)VOCAB * CH);

    const int PB = (NROWS * CH / 2 + 255) / 256;

    embed_ln0<<<NROWS, 256>>>(idx, emb, ln0_w, ln0_b, x);

    for (int i = 0; i < NLAYER; i++) {
        size_t oc = (size_t)i * CH;
        size_t wk = OW_ATTK + (size_t)i * CCH;
        size_t wv = OW_ATTV + (size_t)i * CCH;
        size_t wr = OW_ATTR + (size_t)i * CCH;
        size_t wo = OW_ATTO + (size_t)i * CCH;
        size_t fk = OW_FK   + (size_t)i * FCH;
        size_t fv = OW_FV   + (size_t)i * FCH;
        size_t fr = OW_FR   + (size_t)i * CCH;

        // ---- TimeMix ----
        ln_rows<<<NROWS, 256>>>(x, h, ln1_w + oc, ln1_b + oc);
        mix_time_kernel<<<PB, 256>>>(h, tmk + oc, tmv + oc, tmr + oc,
                                     xkh, xkl, xvh, xvl, xrh, xrl);
        {
            GJobs j;
            j.j[0] = { xkh, xkl, whi + wk, wlo + wk, kb, nullptr, nullptr };
            j.j[1] = { xvh, xvl, whi + wv, wlo + wv, vb, nullptr, nullptr };
            j.j[2] = { xrh, xrl, whi + wr, wlo + wr, rb, nullptr, nullptr };
            dim3 g(CH / 256, NROWS / 128, 3);
            gemm_mma<EPI_NONE><<<g, 256, GSMEM>>>(j, nullptr, nullptr, NROWS, CH, CH);
        }
        wkv_kernel<<<(BATCH * CH + 255) / 256, 256>>>(time_decay + oc, time_first + oc,
                                                      kb, vb, wkvb);
        gate_pair<<<PB, 256>>>(rb, wkvb, gwh, gwl);
        launch_g<EPI_ADD>(gwh, gwl, whi + wo, wlo + wo, x, nullptr, nullptr,
                          x, nullptr, NROWS, CH, CH);

        // ---- ChannelMix ----
        ln_rows<<<NROWS, 256>>>(x, h, ln2_w + oc, ln2_b + oc);
        mix_chan_kernel<<<PB, 256>>>(h, fmk + oc, fmr + oc, xkh, xkl, xrh, xrl);
        launch_g<EPI_RELUSQ>(xkh, xkl, whi + fk, wlo + fk, nullptr, kkh, kkl,
                             nullptr, nullptr, NROWS, FF, CH);
        launch_g<EPI_SIGMOID>(xrh, xrl, whi + fr, wlo + fr, rrb, nullptr, nullptr,
                              nullptr, nullptr, NROWS, CH, CH);
        launch_g<EPI_ADD_MUL>(kkh, kkl, whi + fv, wlo + fv, x, nullptr, nullptr,
                              x, rrb, NROWS, CH, FF);
    }

    // final LN + head projection
    ln_rows_pair<<<NROWS, 256>>>(x, hhh, hhl, ln_out_w, ln_out_b);
    launch_g<EPI_NONE>(hhh, hhl, whi + OW_HEAD, wlo + OW_HEAD, out, nullptr, nullptr,
                       nullptr, nullptr, NROWS, VOCAB, CH);
}

// round 4
// speedup vs baseline: 3.6345x; 1.6433x over previous
#include <cuda_runtime.h>
#include <cuda_fp16.h>
#include <math.h>
#include <stdint.h>

// ---------------- problem constants ----------------
constexpr int BATCH  = 2;
constexpr int SEQ    = 2048;
constexpr int CH     = 1024;
constexpr int FF     = 4096;
constexpr int VOCAB  = 32000;
constexpr int NLAYER = 6;
constexpr int NROWS  = BATCH * SEQ;   // 4096

// fp16 weight pool layout
constexpr size_t CCH = (size_t)CH * CH;
constexpr size_t FCH = (size_t)FF * CH;
constexpr size_t OW_ATTK = 0;
constexpr size_t OW_ATTV = OW_ATTK + 6 * CCH;
constexpr size_t OW_ATTR = OW_ATTV + 6 * CCH;
constexpr size_t OW_ATTO = OW_ATTR + 6 * CCH;
constexpr size_t OW_FK   = OW_ATTO + 6 * CCH;
constexpr size_t OW_FV   = OW_FK   + 6 * FCH;
constexpr size_t OW_FR   = OW_FV   + 6 * FCH;
constexpr size_t OW_HEAD = OW_FR   + 6 * CCH;
constexpr size_t W_TOTAL = OW_HEAD + (size_t)VOCAB * CH;

// ---------------- scratch (device globals; no runtime allocation) ----------
__device__ __align__(256) float g_x  [NROWS * CH];
__device__ __align__(256) float g_h  [NROWS * CH];
__device__ __align__(256) float g_k  [NROWS * CH];
__device__ __align__(256) float g_v  [NROWS * CH];
__device__ __align__(256) float g_r  [NROWS * CH];
__device__ __align__(256) float g_wkv[NROWS * CH];
__device__ __align__(256) float g_rr [NROWS * CH];

__device__ __align__(256) __half g_w  [W_TOTAL];
__device__ __align__(256) __half g_xk [NROWS * CH];
__device__ __align__(256) __half g_xv [NROWS * CH];
__device__ __align__(256) __half g_xr [NROWS * CH];
__device__ __align__(256) __half g_gw [NROWS * CH];
__device__ __align__(256) __half g_hh [NROWS * CH];
__device__ __align__(256) __half g_kk [NROWS * FF];

// ---------------- small helpers ---------------------------------------------
__device__ __forceinline__ uint32_t smem_u32(const void* p) {
    uint32_t a;
    asm("{ .reg .u64 t; cvta.to.shared.u64 t, %1; cvt.u32.u64 %0, t; }"
        : "=r"(a) : "l"(p));
    return a;
}
__device__ __forceinline__ void store_h2(__half* __restrict__ H, size_t e,
                                         float v0, float v1) {
    *reinterpret_cast<__half2*>(H + e) = __floats2half2_rn(v0, v1);
}

// ---------------- weight fp32 -> fp16 (single launch, 8 segments) ------------
struct CvtJobs {
    const float* src[8];
    __half*      dst[8];
    int          n4[8];
};
__global__ void cvt_all(CvtJobs jobs)
{
    int seg = blockIdx.y;
    const float* src = jobs.src[seg];
    __half* dst = jobs.dst[seg];
    int n4 = jobs.n4[seg];
    for (int i = blockIdx.x * 256 + threadIdx.x; i < n4; i += gridDim.x * 256) {
        float4 v = reinterpret_cast<const float4*>(src)[i];
        __half2 a = __floats2half2_rn(v.x, v.y);
        __half2 b = __floats2half2_rn(v.z, v.w);
        uint2 u;
        u.x = *reinterpret_cast<uint32_t*>(&a);
        u.y = *reinterpret_cast<uint32_t*>(&b);
        reinterpret_cast<uint2*>(dst)[i] = u;
    }
}

// ================= tensor-core GEMM (mma.sync fp16, single term) ============
// C[M,N] = A[M,K] * B[N,K]^T ; fp16 operands, fp32 accumulate.
// CTA tile 128x256, BK=64, 256 threads, warps 2x4 (warp tile 64x64), 3 stages.
constexpr int ST_A   = 128 * 64 * 2;           // 16384
constexpr int ST_B   = 256 * 64 * 2;           // 32768
constexpr int STAGE  = ST_A + ST_B;            // 49152
constexpr int NSTG   = 3;
constexpr int GSMEM  = NSTG * STAGE;           // 147456

enum { EPI_NONE = 0, EPI_RELUSQ = 1, EPI_SIGMOID = 2, EPI_ADD = 3, EPI_ADD_MUL = 4 };

struct GJob {
    const __half *A, *B;
    float* C;
    __half* Ch;
};
struct GJobs { GJob j[3]; };

__device__ __forceinline__ void cp16(uint32_t dst, const void* src) {
    asm volatile("cp.async.cg.shared.global [%0], [%1], 16;" :: "r"(dst), "l"(src));
}
__device__ __forceinline__ void ldsm4(uint32_t* r, uint32_t addr) {
    asm volatile("ldmatrix.sync.aligned.m8n8.x4.shared.b16 {%0,%1,%2,%3}, [%4];"
                 : "=r"(r[0]), "=r"(r[1]), "=r"(r[2]), "=r"(r[3]) : "r"(addr));
}
__device__ __forceinline__ void mma16816(float* c, const uint32_t* a, const uint32_t* b) {
    asm volatile(
        "mma.sync.aligned.m16n8k16.row.col.f32.f16.f16.f32 "
        "{%0,%1,%2,%3}, {%4,%5,%6,%7}, {%8,%9}, {%0,%1,%2,%3};"
        : "+f"(c[0]), "+f"(c[1]), "+f"(c[2]), "+f"(c[3])
        : "r"(a[0]), "r"(a[1]), "r"(a[2]), "r"(a[3]), "r"(b[0]), "r"(b[1]));
}

template <int EPI>
__global__ void __launch_bounds__(256, 1)
gemm_mma(GJobs jobs, const float* __restrict__ Res, const float* __restrict__ Mul,
         int M, int N, int K)
{
    extern __shared__ char smem[];
    const uint32_t sb = smem_u32(smem);
    const GJob jb = jobs.j[blockIdx.z];

    const int tid  = threadIdx.x;
    const int lane = tid & 31;
    const int w    = tid >> 5;
    const int wr   = w >> 2;          // 0..1 (M)
    const int wc   = w & 3;           // 0..3 (N)
    const int bm   = blockIdx.y;
    const int bn   = blockIdx.x;

    const int nk = K >> 6;

    // ---- cp.async stage fill -----------------------------------------------
    const int jj = tid & 7;           // 16B chunk in 128B row
    const int rg = tid >> 3;          // 0..31
    const __half* Ag = jb.A + (size_t)bm * 128 * K;
    const __half* Bg = jb.B + (size_t)bn * 256 * K;

    auto issue = [&](int kt, int st) {
        const uint32_t base = sb + (uint32_t)st * STAGE;
        const size_t kof = (size_t)kt * 64 + jj * 8;
#pragma unroll
        for (int it = 0; it < 4; it++) {
            int r = rg + it * 32;
            cp16(base + r * 128 + (uint32_t)((jj ^ (r & 7)) << 4),
                 Ag + (size_t)r * K + kof);
        }
#pragma unroll
        for (int it = 0; it < 8; it++) {
            int r = rg + it * 32;
            cp16(base + ST_A + r * 128 + (uint32_t)((jj ^ (r & 7)) << 4),
                 Bg + (size_t)r * K + kof);
        }
    };

    // ---- fragment address precompute -----------------------------------------
    const int sel = lane >> 3, r8 = lane & 7;
    uint32_t a_row[4], b_row[4], a_chk[4], b_chk[4];
#pragma unroll
    for (int mt = 0; mt < 4; mt++)
        a_row[mt] = (uint32_t)((wr * 64 + mt * 16 + (sel & 1) * 8 + r8) * 128);
#pragma unroll
    for (int np = 0; np < 4; np++)
        b_row[np] = (uint32_t)((wc * 64 + np * 16 + (sel >> 1) * 8 + r8) * 128);
#pragma unroll
    for (int ks = 0; ks < 4; ks++) {
        a_chk[ks] = (uint32_t)(((ks * 2 + (sel >> 1)) ^ r8) << 4);
        b_chk[ks] = (uint32_t)(((ks * 2 + (sel & 1)) ^ r8) << 4);
    }

    float acc[4][8][4];
#pragma unroll
    for (int mt = 0; mt < 4; mt++)
#pragma unroll
        for (int nt = 0; nt < 8; nt++)
#pragma unroll
            for (int q = 0; q < 4; q++) acc[mt][nt][q] = 0.f;

    auto compute = [&](int st) {
        const uint32_t sbase = sb + (uint32_t)st * STAGE;
#pragma unroll
        for (int ks = 0; ks < 4; ks++) {
            uint32_t a[4][4];
#pragma unroll
            for (int mt = 0; mt < 4; mt++)
                ldsm4(a[mt], sbase + a_row[mt] + a_chk[ks]);
            uint32_t b[8][2];
#pragma unroll
            for (int np = 0; np < 4; np++) {
                uint32_t t[4];
                ldsm4(t, sbase + ST_A + b_row[np] + b_chk[ks]);
                b[2*np][0]   = t[0]; b[2*np][1]   = t[1];
                b[2*np+1][0] = t[2]; b[2*np+1][1] = t[3];
            }
#pragma unroll
            for (int mt = 0; mt < 4; mt++)
#pragma unroll
                for (int nt = 0; nt < 8; nt++)
                    mma16816(acc[mt][nt], a[mt], b[nt]);
        }
    };

    // ---- 3-stage pipelined mainloop ---------------------------------------------
    issue(0, 0);
    asm volatile("cp.async.commit_group;" ::: "memory");
    issue(1, 1);
    asm volatile("cp.async.commit_group;" ::: "memory");

    int st = 0;
    for (int kt = 0; kt < nk; kt++) {
        if (kt + 1 < nk) {
            asm volatile("cp.async.wait_group 1;" ::: "memory");
        } else {
            asm volatile("cp.async.wait_group 0;" ::: "memory");
        }
        __syncthreads();
        compute(st);
        if (kt + 2 < nk) {
            int ns = st + 2; if (ns >= NSTG) ns -= NSTG;
            issue(kt + 2, ns);
            asm volatile("cp.async.commit_group;" ::: "memory");
        }
        st = (st + 1 == NSTG) ? 0 : st + 1;
    }

    // ---- epilogue -----------------------------------------------------------------
    const int r0    = bm * 128 + wr * 64 + (lane >> 2);
    const int cbase = bn * 256 + wc * 64 + (lane & 3) * 2;
#pragma unroll
    for (int mt = 0; mt < 4; mt++) {
#pragma unroll
        for (int nt = 0; nt < 8; nt++) {
            int r = r0 + mt * 16;
            int c = cbase + nt * 8;
#pragma unroll
            for (int half = 0; half < 2; half++) {
                int rr2 = r + half * 8;
                float v0 = acc[mt][nt][half * 2 + 0];
                float v1 = acc[mt][nt][half * 2 + 1];
                size_t off = (size_t)rr2 * N + c;
                if (EPI == EPI_RELUSQ) {
                    float t0 = v0 > 0.f ? v0 : 0.f; v0 = t0 * t0;
                    float t1 = v1 > 0.f ? v1 : 0.f; v1 = t1 * t1;
                    store_h2(jb.Ch, off, v0, v1);
                } else {
                    if (EPI == EPI_SIGMOID) {
                        v0 = 1.f / (1.f + expf(-v0));
                        v1 = 1.f / (1.f + expf(-v1));
                    } else if (EPI == EPI_ADD) {
                        float2 rv = *(const float2*)(Res + off);
                        v0 += rv.x; v1 += rv.y;
                    } else if (EPI == EPI_ADD_MUL) {
                        float2 rv = *(const float2*)(Res + off);
                        float2 mv = *(const float2*)(Mul + off);
                        v0 = rv.x + mv.x * v0; v1 = rv.y + mv.y * v1;
                    }
                    *(float2*)(jb.C + off) = make_float2(v0, v1);
                }
            }
        }
    }
}

// ---------------- layernorm -------------------------------------------------
__device__ __forceinline__ void ln_stats(const float* __restrict__ xp,
                                         float& mean, float& inv)
{
    float s = 0.f, s2 = 0.f;
    for (int i = threadIdx.x; i < CH; i += 256) {
        float v = xp[i];
        s += v; s2 += v * v;
    }
#pragma unroll
    for (int o = 16; o > 0; o >>= 1) {
        s  += __shfl_down_sync(0xffffffffu, s,  o);
        s2 += __shfl_down_sync(0xffffffffu, s2, o);
    }
    __shared__ float sh[2][8];
    int warp = threadIdx.x >> 5, lane = threadIdx.x & 31;
    if (lane == 0) { sh[0][warp] = s; sh[1][warp] = s2; }
    __syncthreads();
    float tot = 0.f, tot2 = 0.f;
#pragma unroll
    for (int i = 0; i < 8; i++) { tot += sh[0][i]; tot2 += sh[1][i]; }
    mean = tot * (1.f / CH);
    float var = tot2 * (1.f / CH) - mean * mean;
    inv = rsqrtf(fmaxf(var, 0.f) + 1e-5f);
}

__global__ void ln_rows(const float* __restrict__ in, float* __restrict__ out,
                        const float* __restrict__ w, const float* __restrict__ b)
{
    const float* xp = in + (size_t)blockIdx.x * CH;
    float* op = out + (size_t)blockIdx.x * CH;
    float mean, inv;
    ln_stats(xp, mean, inv);
    for (int i = threadIdx.x; i < CH; i += 256)
        op[i] = (xp[i] - mean) * inv * w[i] + b[i];
}

__global__ void ln_rows_h(const float* __restrict__ in, __half* __restrict__ oh,
                          const float* __restrict__ w, const float* __restrict__ b)
{
    const size_t row = blockIdx.x;
    const float* xp = in + row * CH;
    float mean, inv;
    ln_stats(xp, mean, inv);
    for (int i = threadIdx.x * 2; i < CH; i += 512) {
        float v0 = (xp[i]   - mean) * inv * w[i]   + b[i];
        float v1 = (xp[i+1] - mean) * inv * w[i+1] + b[i+1];
        store_h2(oh, row * CH + i, v0, v1);
    }
}

__global__ void embed_ln0(const int* __restrict__ idx, const float* __restrict__ emb,
                          const float* __restrict__ w, const float* __restrict__ b,
                          float* __restrict__ out)
{
    int tok = idx[blockIdx.x];
    const float* xp = emb + (size_t)tok * CH;
    float* op = out + (size_t)blockIdx.x * CH;
    float mean, inv;
    ln_stats(xp, mean, inv);
    for (int i = threadIdx.x; i < CH; i += 256)
        op[i] = (xp[i] - mean) * inv * w[i] + b[i];
}

// ---------------- token-shift mixing (emit fp16) -----------------------------
__global__ void mix_time_kernel(const float* __restrict__ h,
                                const float* __restrict__ mk,
                                const float* __restrict__ mv,
                                const float* __restrict__ mr,
                                __half* __restrict__ xk,
                                __half* __restrict__ xv,
                                __half* __restrict__ xr)
{
    int p = blockIdx.x * blockDim.x + threadIdx.x;
    if (p >= NROWS * CH / 2) return;
    size_t e = (size_t)p * 2;
    int c = (int)(e & (CH - 1));
    int t = (int)((e >> 10) & (SEQ - 1));
    float h0 = h[e], h1 = h[e + 1];
    float p0 = (t == 0) ? 0.f : h[e - CH];
    float p1 = (t == 0) ? 0.f : h[e - CH + 1];
    float a0 = mk[c], a1 = mk[c+1];
    store_h2(xk, e, h0 * a0 + p0 * (1.f - a0), h1 * a1 + p1 * (1.f - a1));
    float m0 = mv[c], m1 = mv[c+1];
    store_h2(xv, e, h0 * m0 + p0 * (1.f - m0), h1 * m1 + p1 * (1.f - m1));
    float r0 = mr[c], r1 = mr[c+1];
    store_h2(xr, e, h0 * r0 + p0 * (1.f - r0), h1 * r1 + p1 * (1.f - r1));
}

__global__ void mix_chan_kernel(const float* __restrict__ h,
                                const float* __restrict__ mk,
                                const float* __restrict__ mr,
                                __half* __restrict__ xk,
                                __half* __restrict__ xr)
{
    int p = blockIdx.x * blockDim.x + threadIdx.x;
    if (p >= NROWS * CH / 2) return;
    size_t e = (size_t)p * 2;
    int c = (int)(e & (CH - 1));
    int t = (int)((e >> 10) & (SEQ - 1));
    float h0 = h[e], h1 = h[e + 1];
    float p0 = (t == 0) ? 0.f : h[e - CH];
    float p1 = (t == 0) ? 0.f : h[e - CH + 1];
    float a0 = mk[c], a1 = mk[c+1];
    store_h2(xk, e, h0 * a0 + p0 * (1.f - a0), h1 * a1 + p1 * (1.f - a1));
    float r0 = mr[c], r1 = mr[c+1];
    store_h2(xr, e, h0 * r0 + p0 * (1.f - r0), h1 * r1 + p1 * (1.f - r1));
}

// ---------------- gating: out = sigmoid(r) * wkv (fp16) ----------------------
__global__ void gate_h(const float* __restrict__ r, const float* __restrict__ wkv,
                       __half* __restrict__ g)
{
    int p = blockIdx.x * blockDim.x + threadIdx.x;
    if (p >= NROWS * CH / 2) return;
    size_t e = (size_t)p * 2;
    float v0 = wkv[e]     / (1.f + expf(-r[e]));
    float v1 = wkv[e + 1] / (1.f + expf(-r[e + 1]));
    store_h2(g, e, v0, v1);
}

// ---------------- WKV recurrence ---------------------------------------------
__global__ void wkv_kernel(const float* __restrict__ td, const float* __restrict__ tf,
                           const float* __restrict__ k, const float* __restrict__ v,
                           float* __restrict__ y)
{
    int g = blockIdx.x * blockDim.x + threadIdx.x;
    if (g >= BATCH * CH) return;
    int b = g / CH, c = g % CH;
    float w = -expf(td[c]);
    float u = tf[c];
    const float* kp = k + (size_t)b * SEQ * CH + c;
    const float* vp = v + (size_t)b * SEQ * CH + c;
    float*       yp = y + (size_t)b * SEQ * CH + c;
    float a = 0.f, bb = 0.f, p = -1e38f;
#pragma unroll 4
    for (int t = 0; t < SEQ; t++) {
        float kt = kp[(size_t)t * CH];
        float vt = vp[(size_t)t * CH];
        float ww = u + kt;
        float q  = fmaxf(p, ww);
        float e1 = expf(p - q);
        float e2 = expf(ww - q);
        yp[(size_t)t * CH] = (e1 * a + e2 * vt) / (e1 * bb + e2);
        float ww2 = p + w;
        float q2  = fmaxf(ww2, kt);
        float e1b = expf(ww2 - q2);
        float e2b = expf(kt - q2);
        a  = e1b * a  + e2b * vt;
        bb = e1b * bb + e2b;
        p  = q2;
    }
}

// ---------------- launch helpers ---------------------------------------------
template <int EPI>
static void launch_g(const __half* A, const __half* B, float* C, __half* Ch,
                     const float* Res, const float* Mul, int M, int N, int K)
{
    GJobs j;
    j.j[0] = { A, B, C, Ch };
    j.j[1] = j.j[0]; j.j[2] = j.j[0];
    dim3 g(N / 256, M / 128, 1);
    gemm_mma<EPI><<<g, 256, GSMEM>>>(j, Res, Mul, M, N, K);
}

// ---------------- host orchestration ------------------------------------------
extern "C" void kernel_launch(void* const* d_in, const int* in_sizes, int n_in,
                              void* d_out, int out_size)
{
    (void)in_sizes; (void)n_in; (void)out_size;

    const int*   idx        = (const int*)  d_in[0];
    const float* emb        = (const float*)d_in[1];
    const float* ln0_w      = (const float*)d_in[2];
    const float* ln0_b      = (const float*)d_in[3];
    const float* ln1_w      = (const float*)d_in[4];
    const float* ln1_b      = (const float*)d_in[5];
    const float* ln2_w      = (const float*)d_in[6];
    const float* ln2_b      = (const float*)d_in[7];
    const float* time_decay = (const float*)d_in[8];
    const float* time_first = (const float*)d_in[9];
    const float* tmk        = (const float*)d_in[10];
    const float* tmv        = (const float*)d_in[11];
    const float* tmr        = (const float*)d_in[12];
    const float* att_Wk     = (const float*)d_in[13];
    const float* att_Wv     = (const float*)d_in[14];
    const float* att_Wr     = (const float*)d_in[15];
    const float* att_Wo     = (const float*)d_in[16];
    const float* fmk        = (const float*)d_in[17];
    const float* fmr        = (const float*)d_in[18];
    const float* ffn_Wk     = (const float*)d_in[19];
    const float* ffn_Wr     = (const float*)d_in[20];
    const float* ffn_Wv     = (const float*)d_in[21];
    const float* ln_out_w   = (const float*)d_in[22];
    const float* ln_out_b   = (const float*)d_in[23];
    const float* head_w     = (const float*)d_in[24];
    float* out = (float*)d_out;

    cudaFuncSetAttribute(gemm_mma<EPI_NONE>,    cudaFuncAttributeMaxDynamicSharedMemorySize, GSMEM);
    cudaFuncSetAttribute(gemm_mma<EPI_RELUSQ>,  cudaFuncAttributeMaxDynamicSharedMemorySize, GSMEM);
    cudaFuncSetAttribute(gemm_mma<EPI_SIGMOID>, cudaFuncAttributeMaxDynamicSharedMemorySize, GSMEM);
    cudaFuncSetAttribute(gemm_mma<EPI_ADD>,     cudaFuncAttributeMaxDynamicSharedMemorySize, GSMEM);
    cudaFuncSetAttribute(gemm_mma<EPI_ADD_MUL>, cudaFuncAttributeMaxDynamicSharedMemorySize, GSMEM);

    float *x, *h, *kb, *vb, *rb, *wkvb, *rrb;
    cudaGetSymbolAddress((void**)&x,    g_x);
    cudaGetSymbolAddress((void**)&h,    g_h);
    cudaGetSymbolAddress((void**)&kb,   g_k);
    cudaGetSymbolAddress((void**)&vb,   g_v);
    cudaGetSymbolAddress((void**)&rb,   g_r);
    cudaGetSymbolAddress((void**)&wkvb, g_wkv);
    cudaGetSymbolAddress((void**)&rrb,  g_rr);

    __half *wp, *xk, *xv, *xr, *gw, *hh, *kk;
    cudaGetSymbolAddress((void**)&wp, g_w);
    cudaGetSymbolAddress((void**)&xk, g_xk);
    cudaGetSymbolAddress((void**)&xv, g_xv);
    cudaGetSymbolAddress((void**)&xr, g_xr);
    cudaGetSymbolAddress((void**)&gw, g_gw);
    cudaGetSymbolAddress((void**)&hh, g_hh);
    cudaGetSymbolAddress((void**)&kk, g_kk);

    // ---- single-launch weight conversion ----
    {
        CvtJobs cj;
        cj.src[0] = att_Wk; cj.dst[0] = wp + OW_ATTK; cj.n4[0] = (int)(6 * CCH / 4);
        cj.src[1] = att_Wv; cj.dst[1] = wp + OW_ATTV; cj.n4[1] = (int)(6 * CCH / 4);
        cj.src[2] = att_Wr; cj.dst[2] = wp + OW_ATTR; cj.n4[2] = (int)(6 * CCH / 4);
        cj.src[3] = att_Wo; cj.dst[3] = wp + OW_ATTO; cj.n4[3] = (int)(6 * CCH / 4);
        cj.src[4] = ffn_Wk; cj.dst[4] = wp + OW_FK;   cj.n4[4] = (int)(6 * FCH / 4);
        cj.src[5] = ffn_Wv; cj.dst[5] = wp + OW_FV;   cj.n4[5] = (int)(6 * FCH / 4);
        cj.src[6] = ffn_Wr; cj.dst[6] = wp + OW_FR;   cj.n4[6] = (int)(6 * CCH / 4);
        cj.src[7] = head_w; cj.dst[7] = wp + OW_HEAD; cj.n4[7] = (int)((size_t)VOCAB * CH / 4);
        dim3 g(1024, 8);
        cvt_all<<<g, 256>>>(cj);
    }

    const int PB = (NROWS * CH / 2 + 255) / 256;

    embed_ln0<<<NROWS, 256>>>(idx, emb, ln0_w, ln0_b, x);

    for (int i = 0; i < NLAYER; i++) {
        size_t oc = (size_t)i * CH;
        size_t wk = OW_ATTK + (size_t)i * CCH;
        size_t wv = OW_ATTV + (size_t)i * CCH;
        size_t wr = OW_ATTR + (size_t)i * CCH;
        size_t wo = OW_ATTO + (size_t)i * CCH;
        size_t fk = OW_FK   + (size_t)i * FCH;
        size_t fv = OW_FV   + (size_t)i * FCH;
        size_t fr = OW_FR   + (size_t)i * CCH;

        // ---- TimeMix ----
        ln_rows<<<NROWS, 256>>>(x, h, ln1_w + oc, ln1_b + oc);
        mix_time_kernel<<<PB, 256>>>(h, tmk + oc, tmv + oc, tmr + oc, xk, xv, xr);
        {
            GJobs j;
            j.j[0] = { xk, wp + wk, kb, nullptr };
            j.j[1] = { xv, wp + wv, vb, nullptr };
            j.j[2] = { xr, wp + wr, rb, nullptr };
            dim3 g(CH / 256, NROWS / 128, 3);
            gemm_mma<EPI_NONE><<<g, 256, GSMEM>>>(j, nullptr, nullptr, NROWS, CH, CH);
        }
        wkv_kernel<<<(BATCH * CH + 255) / 256, 256>>>(time_decay + oc, time_first + oc,
                                                      kb, vb, wkvb);
        gate_h<<<PB, 256>>>(rb, wkvb, gw);
        launch_g<EPI_ADD>(gw, wp + wo, x, nullptr, x, nullptr, NROWS, CH, CH);

        // ---- ChannelMix ----
        ln_rows<<<NROWS, 256>>>(x, h, ln2_w + oc, ln2_b + oc);
        mix_chan_kernel<<<PB, 256>>>(h, fmk + oc, fmr + oc, xk, xr);
        launch_g<EPI_RELUSQ>(xk, wp + fk, nullptr, kk, nullptr, nullptr, NROWS, FF, CH);
        launch_g<EPI_SIGMOID>(xr, wp + fr, rrb, nullptr, nullptr, nullptr, NROWS, CH, CH);
        launch_g<EPI_ADD_MUL>(kk, wp + fv, x, nullptr, x, rrb, NROWS, CH, FF);
    }

    // final LN + head projection
    ln_rows_h<<<NROWS, 256>>>(x, hh, ln_out_w, ln_out_b);
    launch_g<EPI_NONE>(hh, wp + OW_HEAD, out, nullptr, nullptr, nullptr, NROWS, VOCAB, CH);
}

// round 5
// speedup vs baseline: 3.7193x; 1.0233x over previous
#include <cuda_runtime.h>
#include <cuda_fp16.h>
#include <math.h>
#include <stdint.h>

// ---------------- problem constants ----------------
constexpr int BATCH  = 2;
constexpr int SEQ    = 2048;
constexpr int CH     = 1024;
constexpr int FF     = 4096;
constexpr int VOCAB  = 32000;
constexpr int NLAYER = 6;
constexpr int NROWS  = BATCH * SEQ;   // 4096 (M for every GEMM)

// fp16 weight pool layout
constexpr size_t CCH = (size_t)CH * CH;
constexpr size_t FCH = (size_t)FF * CH;
constexpr size_t OW_ATTK = 0;
constexpr size_t OW_ATTV = OW_ATTK + 6 * CCH;
constexpr size_t OW_ATTR = OW_ATTV + 6 * CCH;
constexpr size_t OW_ATTO = OW_ATTR + 6 * CCH;
constexpr size_t OW_FK   = OW_ATTO + 6 * CCH;
constexpr size_t OW_FV   = OW_FK   + 6 * FCH;
constexpr size_t OW_FR   = OW_FV   + 6 * FCH;
constexpr size_t OW_HEAD = OW_FR   + 6 * CCH;
constexpr size_t W_TOTAL = OW_HEAD + (size_t)VOCAB * CH;

// ---------------- scratch (device globals) ----------------------------------
__device__ __align__(256) float g_x  [NROWS * CH];
__device__ __align__(256) float g_k  [NROWS * CH];
__device__ __align__(256) float g_v  [NROWS * CH];
__device__ __align__(256) float g_r  [NROWS * CH];
__device__ __align__(256) float g_wkv[NROWS * CH];
__device__ __align__(256) float g_rr [NROWS * CH];

__device__ __align__(256) __half g_w  [W_TOTAL];
__device__ __align__(256) __half g_xk [NROWS * CH];
__device__ __align__(256) __half g_xv [NROWS * CH];
__device__ __align__(256) __half g_xr [NROWS * CH];
__device__ __align__(256) __half g_gw [NROWS * CH];
__device__ __align__(256) __half g_hh [NROWS * CH];
__device__ __align__(256) __half g_kk [NROWS * FF];

// ---------------- helpers -----------------------------------------------------
__device__ __forceinline__ uint32_t smem_u32(const void* p) {
    uint32_t a;
    asm("{ .reg .u64 t; cvta.to.shared.u64 t, %1; cvt.u32.u64 %0, t; }"
        : "=r"(a) : "l"(p));
    return a;
}
__device__ __forceinline__ void store_h2(__half* __restrict__ H, size_t e,
                                         float v0, float v1) {
    *reinterpret_cast<__half2*>(H + e) = __floats2half2_rn(v0, v1);
}

// ---------------- weight fp32 -> fp16 (single launch) -------------------------
struct CvtJobs {
    const float* src[8];
    __half*      dst[8];
    int          n4[8];
};
__global__ void cvt_all(CvtJobs jobs)
{
    int seg = blockIdx.y;
    const float* src = jobs.src[seg];
    __half* dst = jobs.dst[seg];
    int n4 = jobs.n4[seg];
    for (int i = blockIdx.x * 256 + threadIdx.x; i < n4; i += gridDim.x * 256) {
        float4 v = reinterpret_cast<const float4*>(src)[i];
        __half2 a = __floats2half2_rn(v.x, v.y);
        __half2 b = __floats2half2_rn(v.z, v.w);
        uint2 u;
        u.x = *reinterpret_cast<uint32_t*>(&a);
        u.y = *reinterpret_cast<uint32_t*>(&b);
        reinterpret_cast<uint2*>(dst)[i] = u;
    }
}

// ================= tensor-core GEMM (mma.sync fp16) ==========================
// C[4096,N] = A[4096,K] * B[N,K]^T. CTA tile 128x256, BK=64, 512 threads,
// 16 warps as 4x4 (warp tile 32x64), 3-stage cp.async pipeline.
// Multi-job: one launch covers up to 3 independent GEMMs (tile table).
constexpr int ST_A   = 128 * 64 * 2;           // 16384
constexpr int ST_B   = 256 * 64 * 2;           // 32768
constexpr int STAGE  = ST_A + ST_B;            // 49152
constexpr int NSTG   = 3;
constexpr int GSMEM  = NSTG * STAGE;           // 147456

enum { EPI_NONE = 0, EPI_RELUSQ = 1, EPI_SIGMOID = 2, EPI_ADD = 3, EPI_ADD_MUL = 4 };

struct GJob {
    const __half *A, *B;
    float* C;
    __half* Ch;
    const float *Res, *Mul;
    int N, K, epi, ntx, base;
};
struct GJobs { GJob j[3]; int njobs; };

__device__ __forceinline__ void cp16(uint32_t dst, const void* src) {
    asm volatile("cp.async.cg.shared.global [%0], [%1], 16;" :: "r"(dst), "l"(src));
}
__device__ __forceinline__ void ldsm4(uint32_t* r, uint32_t addr) {
    asm volatile("ldmatrix.sync.aligned.m8n8.x4.shared.b16 {%0,%1,%2,%3}, [%4];"
                 : "=r"(r[0]), "=r"(r[1]), "=r"(r[2]), "=r"(r[3]) : "r"(addr));
}
__device__ __forceinline__ void mma16816(float* c, const uint32_t* a, const uint32_t* b) {
    asm volatile(
        "mma.sync.aligned.m16n8k16.row.col.f32.f16.f16.f32 "
        "{%0,%1,%2,%3}, {%4,%5,%6,%7}, {%8,%9}, {%0,%1,%2,%3};"
        : "+f"(c[0]), "+f"(c[1]), "+f"(c[2]), "+f"(c[3])
        : "r"(a[0]), "r"(a[1]), "r"(a[2]), "r"(a[3]), "r"(b[0]), "r"(b[1]));
}

__global__ void __launch_bounds__(512, 1)
gemm_mma(GJobs jobs)
{
    extern __shared__ char smem[];
    const uint32_t sb = smem_u32(smem);

    // ---- job + tile selection ----
    int id = blockIdx.x;
    int ji = 0;
    if (jobs.njobs > 1 && id >= jobs.j[1].base) ji = 1;
    if (jobs.njobs > 2 && id >= jobs.j[2].base) ji = 2;
    const GJob jb = jobs.j[ji];
    const int local = id - jb.base;
    const int bn = local % jb.ntx;
    const int bm = local / jb.ntx;
    const int N = jb.N, K = jb.K;
    const int nk = K >> 6;

    const int tid  = threadIdx.x;
    const int lane = tid & 31;
    const int w    = tid >> 5;
    const int wr   = w >> 2;          // 0..3 (M, 32 rows each)
    const int wc   = w & 3;           // 0..3 (N, 64 cols each)

    // ---- cp.async stage fill (512 threads) ----
    const int jj = tid & 7;           // 16B chunk within 128B row
    const int rg = tid >> 3;          // 0..63
    const __half* Ag = jb.A + (size_t)bm * 128 * K;
    const __half* Bg = jb.B + (size_t)bn * 256 * K;

    auto issue = [&](int kt, int st) {
        const uint32_t base = sb + (uint32_t)st * STAGE;
        const size_t kof = (size_t)kt * 64 + jj * 8;
#pragma unroll
        for (int it = 0; it < 2; it++) {
            int r = rg + it * 64;
            cp16(base + r * 128 + (uint32_t)((jj ^ (r & 7)) << 4),
                 Ag + (size_t)r * K + kof);
        }
#pragma unroll
        for (int it = 0; it < 4; it++) {
            int r = rg + it * 64;
            cp16(base + ST_A + r * 128 + (uint32_t)((jj ^ (r & 7)) << 4),
                 Bg + (size_t)r * K + kof);
        }
    };

    // ---- fragment addresses ----
    const int sel = lane >> 3, r8 = lane & 7;
    uint32_t a_row[2], b_row[4], a_chk[4], b_chk[4];
#pragma unroll
    for (int mt = 0; mt < 2; mt++)
        a_row[mt] = (uint32_t)((wr * 32 + mt * 16 + (sel & 1) * 8 + r8) * 128);
#pragma unroll
    for (int np = 0; np < 4; np++)
        b_row[np] = (uint32_t)((wc * 64 + np * 16 + (sel >> 1) * 8 + r8) * 128);
#pragma unroll
    for (int ks = 0; ks < 4; ks++) {
        a_chk[ks] = (uint32_t)(((ks * 2 + (sel >> 1)) ^ r8) << 4);
        b_chk[ks] = (uint32_t)(((ks * 2 + (sel & 1)) ^ r8) << 4);
    }

    float acc[2][8][4];
#pragma unroll
    for (int mt = 0; mt < 2; mt++)
#pragma unroll
        for (int nt = 0; nt < 8; nt++)
#pragma unroll
            for (int q = 0; q < 4; q++) acc[mt][nt][q] = 0.f;

    auto compute = [&](int st) {
        const uint32_t sbase = sb + (uint32_t)st * STAGE;
#pragma unroll
        for (int ks = 0; ks < 4; ks++) {
            uint32_t a[2][4];
#pragma unroll
            for (int mt = 0; mt < 2; mt++)
                ldsm4(a[mt], sbase + a_row[mt] + a_chk[ks]);
            uint32_t b[8][2];
#pragma unroll
            for (int np = 0; np < 4; np++) {
                uint32_t t[4];
                ldsm4(t, sbase + ST_A + b_row[np] + b_chk[ks]);
                b[2*np][0]   = t[0]; b[2*np][1]   = t[1];
                b[2*np+1][0] = t[2]; b[2*np+1][1] = t[3];
            }
#pragma unroll
            for (int mt = 0; mt < 2; mt++)
#pragma unroll
                for (int nt = 0; nt < 8; nt++)
                    mma16816(acc[mt][nt], a[mt], b[nt]);
        }
    };

    // ---- 3-stage pipelined mainloop ----
    issue(0, 0);
    asm volatile("cp.async.commit_group;" ::: "memory");
    issue(1, 1);
    asm volatile("cp.async.commit_group;" ::: "memory");

    int st = 0;
    for (int kt = 0; kt < nk; kt++) {
        if (kt + 1 < nk) {
            asm volatile("cp.async.wait_group 1;" ::: "memory");
        } else {
            asm volatile("cp.async.wait_group 0;" ::: "memory");
        }
        __syncthreads();
        compute(st);
        if (kt + 2 < nk) {
            int ns = st + 2; if (ns >= NSTG) ns -= NSTG;
            issue(kt + 2, ns);
            asm volatile("cp.async.commit_group;" ::: "memory");
        }
        st = (st + 1 == NSTG) ? 0 : st + 1;
    }

    // ---- epilogue (runtime epi) ----
    const int r0    = bm * 128 + wr * 32 + (lane >> 2);
    const int cbase = bn * 256 + wc * 64 + (lane & 3) * 2;
    const int epi = jb.epi;
#pragma unroll
    for (int mt = 0; mt < 2; mt++) {
#pragma unroll
        for (int nt = 0; nt < 8; nt++) {
            int r = r0 + mt * 16;
            int c = cbase + nt * 8;
#pragma unroll
            for (int half = 0; half < 2; half++) {
                int rr2 = r + half * 8;
                float v0 = acc[mt][nt][half * 2 + 0];
                float v1 = acc[mt][nt][half * 2 + 1];
                size_t off = (size_t)rr2 * N + c;
                if (epi == EPI_RELUSQ) {
                    float t0 = v0 > 0.f ? v0 : 0.f; v0 = t0 * t0;
                    float t1 = v1 > 0.f ? v1 : 0.f; v1 = t1 * t1;
                    store_h2(jb.Ch, off, v0, v1);
                } else {
                    if (epi == EPI_SIGMOID) {
                        v0 = 1.f / (1.f + expf(-v0));
                        v1 = 1.f / (1.f + expf(-v1));
                    } else if (epi == EPI_ADD) {
                        float2 rv = *(const float2*)(jb.Res + off);
                        v0 += rv.x; v1 += rv.y;
                    } else if (epi == EPI_ADD_MUL) {
                        float2 rv = *(const float2*)(jb.Res + off);
                        float2 mv = *(const float2*)(jb.Mul + off);
                        v0 = rv.x + mv.x * v0; v1 = rv.y + mv.y * v1;
                    }
                    *(float2*)(jb.C + off) = make_float2(v0, v1);
                }
            }
        }
    }
}

// ---------------- fused LN + token-shift mix ---------------------------------
// Each block handles one row t: computes LN stats for row t and row t-1,
// then emits fp16 mixed tensors. Removes the h roundtrip buffer entirely.
__device__ __forceinline__ void ln_stats2(const float* __restrict__ xT,
                                          const float* __restrict__ xP, bool hasP,
                                          float& mnT, float& invT,
                                          float& mnP, float& invP)
{
    float sT = 0.f, s2T = 0.f, sP = 0.f, s2P = 0.f;
    for (int i = threadIdx.x; i < CH; i += 256) {
        float v = xT[i]; sT += v; s2T += v * v;
        if (hasP) { float u = xP[i]; sP += u; s2P += u * u; }
    }
#pragma unroll
    for (int o = 16; o > 0; o >>= 1) {
        sT  += __shfl_down_sync(0xffffffffu, sT,  o);
        s2T += __shfl_down_sync(0xffffffffu, s2T, o);
        sP  += __shfl_down_sync(0xffffffffu, sP,  o);
        s2P += __shfl_down_sync(0xffffffffu, s2P, o);
    }
    __shared__ float sh[4][8];
    int warp = threadIdx.x >> 5, lane = threadIdx.x & 31;
    if (lane == 0) { sh[0][warp] = sT; sh[1][warp] = s2T; sh[2][warp] = sP; sh[3][warp] = s2P; }
    __syncthreads();
    float tT = 0.f, t2T = 0.f, tP = 0.f, t2P = 0.f;
#pragma unroll
    for (int i = 0; i < 8; i++) {
        tT += sh[0][i]; t2T += sh[1][i]; tP += sh[2][i]; t2P += sh[3][i];
    }
    mnT = tT * (1.f / CH);
    invT = rsqrtf(fmaxf(t2T * (1.f / CH) - mnT * mnT, 0.f) + 1e-5f);
    mnP = tP * (1.f / CH);
    invP = rsqrtf(fmaxf(t2P * (1.f / CH) - mnP * mnP, 0.f) + 1e-5f);
}

__global__ void ln_mix_time(const float* __restrict__ x,
                            const float* __restrict__ w, const float* __restrict__ b,
                            const float* __restrict__ mk, const float* __restrict__ mv,
                            const float* __restrict__ mr,
                            __half* __restrict__ xk, __half* __restrict__ xv,
                            __half* __restrict__ xr)
{
    const int row = blockIdx.x;
    const bool hasP = (row & (SEQ - 1)) != 0;
    const float* xT = x + (size_t)row * CH;
    const float* xP = xT - CH;
    float mnT, invT, mnP, invP;
    ln_stats2(xT, xP, hasP, mnT, invT, mnP, invP);
    const size_t rb = (size_t)row * CH;
    for (int i = threadIdx.x * 2; i < CH; i += 512) {
        float hT0 = (xT[i]   - mnT) * invT * w[i]   + b[i];
        float hT1 = (xT[i+1] - mnT) * invT * w[i+1] + b[i+1];
        float hP0 = hasP ? (xP[i]   - mnP) * invP * w[i]   + b[i]   : 0.f;
        float hP1 = hasP ? (xP[i+1] - mnP) * invP * w[i+1] + b[i+1] : 0.f;
        float a0 = mk[i], a1 = mk[i+1];
        store_h2(xk, rb + i, hT0 * a0 + hP0 * (1.f - a0), hT1 * a1 + hP1 * (1.f - a1));
        float m0 = mv[i], m1 = mv[i+1];
        store_h2(xv, rb + i, hT0 * m0 + hP0 * (1.f - m0), hT1 * m1 + hP1 * (1.f - m1));
        float r0 = mr[i], r1 = mr[i+1];
        store_h2(xr, rb + i, hT0 * r0 + hP0 * (1.f - r0), hT1 * r1 + hP1 * (1.f - r1));
    }
}

__global__ void ln_mix_chan(const float* __restrict__ x,
                            const float* __restrict__ w, const float* __restrict__ b,
                            const float* __restrict__ mk, const float* __restrict__ mr,
                            __half* __restrict__ xk, __half* __restrict__ xr)
{
    const int row = blockIdx.x;
    const bool hasP = (row & (SEQ - 1)) != 0;
    const float* xT = x + (size_t)row * CH;
    const float* xP = xT - CH;
    float mnT, invT, mnP, invP;
    ln_stats2(xT, xP, hasP, mnT, invT, mnP, invP);
    const size_t rb = (size_t)row * CH;
    for (int i = threadIdx.x * 2; i < CH; i += 512) {
        float hT0 = (xT[i]   - mnT) * invT * w[i]   + b[i];
        float hT1 = (xT[i+1] - mnT) * invT * w[i+1] + b[i+1];
        float hP0 = hasP ? (xP[i]   - mnP) * invP * w[i]   + b[i]   : 0.f;
        float hP1 = hasP ? (xP[i+1] - mnP) * invP * w[i+1] + b[i+1] : 0.f;
        float a0 = mk[i], a1 = mk[i+1];
        store_h2(xk, rb + i, hT0 * a0 + hP0 * (1.f - a0), hT1 * a1 + hP1 * (1.f - a1));
        float r0 = mr[i], r1 = mr[i+1];
        store_h2(xr, rb + i, hT0 * r0 + hP0 * (1.f - r0), hT1 * r1 + hP1 * (1.f - r1));
    }
}

// ---------------- layernorm (embed + final) ----------------------------------
__device__ __forceinline__ void ln_stats(const float* __restrict__ xp,
                                         float& mean, float& inv)
{
    float s = 0.f, s2 = 0.f;
    for (int i = threadIdx.x; i < CH; i += 256) {
        float v = xp[i];
        s += v; s2 += v * v;
    }
#pragma unroll
    for (int o = 16; o > 0; o >>= 1) {
        s  += __shfl_down_sync(0xffffffffu, s,  o);
        s2 += __shfl_down_sync(0xffffffffu, s2, o);
    }
    __shared__ float sh[2][8];
    int warp = threadIdx.x >> 5, lane = threadIdx.x & 31;
    if (lane == 0) { sh[0][warp] = s; sh[1][warp] = s2; }
    __syncthreads();
    float tot = 0.f, tot2 = 0.f;
#pragma unroll
    for (int i = 0; i < 8; i++) { tot += sh[0][i]; tot2 += sh[1][i]; }
    mean = tot * (1.f / CH);
    float var = tot2 * (1.f / CH) - mean * mean;
    inv = rsqrtf(fmaxf(var, 0.f) + 1e-5f);
}

__global__ void ln_rows_h(const float* __restrict__ in, __half* __restrict__ oh,
                          const float* __restrict__ w, const float* __restrict__ b)
{
    const size_t row = blockIdx.x;
    const float* xp = in + row * CH;
    float mean, inv;
    ln_stats(xp, mean, inv);
    for (int i = threadIdx.x * 2; i < CH; i += 512) {
        float v0 = (xp[i]   - mean) * inv * w[i]   + b[i];
        float v1 = (xp[i+1] - mean) * inv * w[i+1] + b[i+1];
        store_h2(oh, row * CH + i, v0, v1);
    }
}

__global__ void embed_ln0(const int* __restrict__ idx, const float* __restrict__ emb,
                          const float* __restrict__ w, const float* __restrict__ b,
                          float* __restrict__ out)
{
    int tok = idx[blockIdx.x];
    const float* xp = emb + (size_t)tok * CH;
    float* op = out + (size_t)blockIdx.x * CH;
    float mean, inv;
    ln_stats(xp, mean, inv);
    for (int i = threadIdx.x; i < CH; i += 256)
        op[i] = (xp[i] - mean) * inv * w[i] + b[i];
}

// ---------------- gating: out = sigmoid(r) * wkv (fp16) ----------------------
__global__ void gate_h(const float* __restrict__ r, const float* __restrict__ wkv,
                       __half* __restrict__ g)
{
    int p = blockIdx.x * blockDim.x + threadIdx.x;
    if (p >= NROWS * CH / 2) return;
    size_t e = (size_t)p * 2;
    float v0 = wkv[e]     / (1.f + expf(-r[e]));
    float v1 = wkv[e + 1] / (1.f + expf(-r[e + 1]));
    store_h2(g, e, v0, v1);
}

// ---------------- WKV recurrence (one warp-lane per channel, 128 blocks) -----
__global__ void wkv_kernel(const float* __restrict__ td, const float* __restrict__ tf,
                           const float* __restrict__ k, const float* __restrict__ v,
                           float* __restrict__ y)
{
    int g = blockIdx.x * 32 + threadIdx.x;
    if (g >= BATCH * CH) return;
    int b = g / CH, c = g % CH;
    float w = -expf(td[c]);
    float u = tf[c];
    const float* kp = k + (size_t)b * SEQ * CH + c;
    const float* vp = v + (size_t)b * SEQ * CH + c;
    float*       yp = y + (size_t)b * SEQ * CH + c;
    float a = 0.f, bb = 0.f, p = -1e38f;
#pragma unroll 4
    for (int t = 0; t < SEQ; t++) {
        float kt = kp[(size_t)t * CH];
        float vt = vp[(size_t)t * CH];
        float ww = u + kt;
        float q  = fmaxf(p, ww);
        float e1 = expf(p - q);
        float e2 = expf(ww - q);
        yp[(size_t)t * CH] = (e1 * a + e2 * vt) / (e1 * bb + e2);
        float ww2 = p + w;
        float q2  = fmaxf(ww2, kt);
        float e1b = expf(ww2 - q2);
        float e2b = expf(kt - q2);
        a  = e1b * a  + e2b * vt;
        bb = e1b * bb + e2b;
        p  = q2;
    }
}

// ---------------- host orchestration ------------------------------------------
static GJob mkjob(const __half* A, const __half* B, float* C, __half* Ch,
                  const float* Res, const float* Mul, int N, int K, int epi, int base)
{
    GJob j;
    j.A = A; j.B = B; j.C = C; j.Ch = Ch; j.Res = Res; j.Mul = Mul;
    j.N = N; j.K = K; j.epi = epi; j.ntx = N / 256; j.base = base;
    return j;
}

extern "C" void kernel_launch(void* const* d_in, const int* in_sizes, int n_in,
                              void* d_out, int out_size)
{
    (void)in_sizes; (void)n_in; (void)out_size;

    const int*   idx        = (const int*)  d_in[0];
    const float* emb        = (const float*)d_in[1];
    const float* ln0_w      = (const float*)d_in[2];
    const float* ln0_b      = (const float*)d_in[3];
    const float* ln1_w      = (const float*)d_in[4];
    const float* ln1_b      = (const float*)d_in[5];
    const float* ln2_w      = (const float*)d_in[6];
    const float* ln2_b      = (const float*)d_in[7];
    const float* time_decay = (const float*)d_in[8];
    const float* time_first = (const float*)d_in[9];
    const float* tmk        = (const float*)d_in[10];
    const float* tmv        = (const float*)d_in[11];
    const float* tmr        = (const float*)d_in[12];
    const float* att_Wk     = (const float*)d_in[13];
    const float* att_Wv     = (const float*)d_in[14];
    const float* att_Wr     = (const float*)d_in[15];
    const float* att_Wo     = (const float*)d_in[16];
    const float* fmk        = (const float*)d_in[17];
    const float* fmr        = (const float*)d_in[18];
    const float* ffn_Wk     = (const float*)d_in[19];
    const float* ffn_Wr     = (const float*)d_in[20];
    const float* ffn_Wv     = (const float*)d_in[21];
    const float* ln_out_w   = (const float*)d_in[22];
    const float* ln_out_b   = (const float*)d_in[23];
    const float* head_w     = (const float*)d_in[24];
    float* out = (float*)d_out;

    cudaFuncSetAttribute(gemm_mma, cudaFuncAttributeMaxDynamicSharedMemorySize, GSMEM);

    float *x, *kb, *vb, *rb, *wkvb, *rrb;
    cudaGetSymbolAddress((void**)&x,    g_x);
    cudaGetSymbolAddress((void**)&kb,   g_k);
    cudaGetSymbolAddress((void**)&vb,   g_v);
    cudaGetSymbolAddress((void**)&rb,   g_r);
    cudaGetSymbolAddress((void**)&wkvb, g_wkv);
    cudaGetSymbolAddress((void**)&rrb,  g_rr);

    __half *wp, *xk, *xv, *xr, *gw, *hh, *kk;
    cudaGetSymbolAddress((void**)&wp, g_w);
    cudaGetSymbolAddress((void**)&xk, g_xk);
    cudaGetSymbolAddress((void**)&xv, g_xv);
    cudaGetSymbolAddress((void**)&xr, g_xr);
    cudaGetSymbolAddress((void**)&gw, g_gw);
    cudaGetSymbolAddress((void**)&hh, g_hh);
    cudaGetSymbolAddress((void**)&kk, g_kk);

    // ---- single-launch weight conversion ----
    {
        CvtJobs cj;
        cj.src[0] = att_Wk; cj.dst[0] = wp + OW_ATTK; cj.n4[0] = (int)(6 * CCH / 4);
        cj.src[1] = att_Wv; cj.dst[1] = wp + OW_ATTV; cj.n4[1] = (int)(6 * CCH / 4);
        cj.src[2] = att_Wr; cj.dst[2] = wp + OW_ATTR; cj.n4[2] = (int)(6 * CCH / 4);
        cj.src[3] = att_Wo; cj.dst[3] = wp + OW_ATTO; cj.n4[3] = (int)(6 * CCH / 4);
        cj.src[4] = ffn_Wk; cj.dst[4] = wp + OW_FK;   cj.n4[4] = (int)(6 * FCH / 4);
        cj.src[5] = ffn_Wv; cj.dst[5] = wp + OW_FV;   cj.n4[5] = (int)(6 * FCH / 4);
        cj.src[6] = ffn_Wr; cj.dst[6] = wp + OW_FR;   cj.n4[6] = (int)(6 * CCH / 4);
        cj.src[7] = head_w; cj.dst[7] = wp + OW_HEAD; cj.n4[7] = (int)((size_t)VOCAB * CH / 4);
        dim3 g(1024, 8);
        cvt_all<<<g, 256>>>(cj);
    }

    const int PB = (NROWS * CH / 2 + 255) / 256;
    const int TCC = (NROWS / 128) * (CH / 256);   // 128 tiles for N=1024 GEMM
    const int TFF = (NROWS / 128) * (FF / 256);   // 512 tiles for N=4096 GEMM

    embed_ln0<<<NROWS, 256>>>(idx, emb, ln0_w, ln0_b, x);

    for (int i = 0; i < NLAYER; i++) {
        size_t oc = (size_t)i * CH;
        const __half* Wk = wp + OW_ATTK + (size_t)i * CCH;
        const __half* Wv = wp + OW_ATTV + (size_t)i * CCH;
        const __half* Wr = wp + OW_ATTR + (size_t)i * CCH;
        const __half* Wo = wp + OW_ATTO + (size_t)i * CCH;
        const __half* Fk = wp + OW_FK   + (size_t)i * FCH;
        const __half* Fv = wp + OW_FV   + (size_t)i * FCH;
        const __half* Fr = wp + OW_FR   + (size_t)i * CCH;

        // ---- TimeMix ----
        ln_mix_time<<<NROWS, 256>>>(x, ln1_w + oc, ln1_b + oc,
                                    tmk + oc, tmv + oc, tmr + oc, xk, xv, xr);
        {
            GJobs j;
            j.njobs = 3;
            j.j[0] = mkjob(xk, Wk, kb, nullptr, nullptr, nullptr, CH, CH, EPI_NONE, 0);
            j.j[1] = mkjob(xv, Wv, vb, nullptr, nullptr, nullptr, CH, CH, EPI_NONE, TCC);
            j.j[2] = mkjob(xr, Wr, rb, nullptr, nullptr, nullptr, CH, CH, EPI_NONE, 2 * TCC);
            gemm_mma<<<3 * TCC, 512, GSMEM>>>(j);
        }
        wkv_kernel<<<BATCH * CH / 32, 32>>>(time_decay + oc, time_first + oc, kb, vb, wkvb);
        gate_h<<<PB, 256>>>(rb, wkvb, gw);
        {
            GJobs j;
            j.njobs = 1;
            j.j[0] = mkjob(gw, Wo, x, nullptr, x, nullptr, CH, CH, EPI_ADD, 0);
            gemm_mma<<<TCC, 512, GSMEM>>>(j);
        }

        // ---- ChannelMix ----
        ln_mix_chan<<<NROWS, 256>>>(x, ln2_w + oc, ln2_b + oc, fmk + oc, fmr + oc, xk, xr);
        {
            GJobs j;
            j.njobs = 2;
            j.j[0] = mkjob(xk, Fk, nullptr, kk, nullptr, nullptr, FF, CH, EPI_RELUSQ, 0);
            j.j[1] = mkjob(xr, Fr, rrb, nullptr, nullptr, nullptr, CH, CH, EPI_SIGMOID, TFF);
            gemm_mma<<<TFF + TCC, 512, GSMEM>>>(j);
        }
        {
            GJobs j;
            j.njobs = 1;
            j.j[0] = mkjob(kk, Fv, x, nullptr, x, rrb, CH, FF, EPI_ADD_MUL, 0);
            gemm_mma<<<TCC, 512, GSMEM>>>(j);
        }
    }

    // final LN + head projection
    ln_rows_h<<<NROWS, 256>>>(x, hh, ln_out_w, ln_out_b);
    {
        GJobs j;
        j.njobs = 1;
        j.j[0] = mkjob(hh, wp + OW_HEAD, out, nullptr, nullptr, nullptr,
                       VOCAB, CH, EPI_NONE, 0);
        gemm_mma<<<(NROWS / 128) * (VOCAB / 256), 512, GSMEM>>>(j);
    }
}